// round 1
// baseline (speedup 1.0000x reference)
#include <cuda_runtime.h>
#include <math.h>

// Problem constants (fixed by reference: B=8, H=W=64, Cin=Cout=512)
#define BATCH 8
#define GH 64
#define GW 64
#define NNODE 4096            // GH*GW
#define CCH 512
#define MROWS (BATCH * NNODE) // 32768
#define EPSV 1e-5f

// ---------------- scratch (static device globals; no allocation) ----------------
__device__ float g_residual[MROWS * CCH]; // 64 MiB
__device__ float g_buf1[MROWS * CCH];     // 64 MiB
__device__ float g_buf2[MROWS * CCH];     // 64 MiB
__device__ float g_pool_part[128 * CCH];  // pool partials: 8 batches x 16 slices
__device__ float g_xg[BATCH * CCH];
__device__ float g_ps[128 * CCH];         // BN2 partial sums
__device__ float g_pq[128 * CCH];         // BN2 partial sumsq
__device__ float g_scale[CCH];
__device__ float g_shift[CCH];

// ---------------- SGEMM: C[M,512] = A[M,512] @ B[512,512] (+bias)(+relu) --------
// 128x128 tile, BK=8, 256 threads, 8x8 register tile, double-buffered smem.
#define BM 128
#define BNT 128
#define BK 8
#define TM 8
#define TN 8
#define GN 512
#define GK 512

__global__ __launch_bounds__(256, 2)
void sgemm_kernel(const float* __restrict__ A, const float* __restrict__ B,
                  float* __restrict__ C, const float* __restrict__ bias, int relu)
{
    __shared__ float As[2][BK][BM];
    __shared__ float Bs[2][BK][BNT];

    const int bx = blockIdx.x;   // N tile (0..3)
    const int by = blockIdx.y;   // M tile (0..255)
    const int tid = threadIdx.x;

    // A load mapping: 128 rows x 8 k, one float4 per thread
    const int a_row = tid >> 1;
    const int a_k   = (tid & 1) * 4;
    // B load mapping: 8 k-rows x 128 cols, one float4 per thread
    const int b_k   = tid >> 5;
    const int b_col = (tid & 31) * 4;

    const float* Aptr = A + ((size_t)(by * BM + a_row)) * GK + a_k;
    const float* Bptr = B + (size_t)b_k * GN + bx * BNT + b_col;

    const int tx = tid & 15;
    const int ty = tid >> 4;

    float acc[TM][TN];
    #pragma unroll
    for (int i = 0; i < TM; i++)
        #pragma unroll
        for (int j = 0; j < TN; j++) acc[i][j] = 0.f;

    // prologue: tile 0
    {
        float4 av = *(const float4*)Aptr;
        float4 bv = *(const float4*)Bptr;
        As[0][a_k + 0][a_row] = av.x;
        As[0][a_k + 1][a_row] = av.y;
        As[0][a_k + 2][a_row] = av.z;
        As[0][a_k + 3][a_row] = av.w;
        *(float4*)&Bs[0][b_k][b_col] = bv;
    }
    __syncthreads();

    const int T = GK / BK;  // 64
    int buf = 0;
    for (int t = 0; t < T; ++t) {
        float4 av, bv;
        const bool more = (t + 1 < T);
        if (more) {
            av = *(const float4*)(Aptr + (t + 1) * BK);
            bv = *(const float4*)(Bptr + (size_t)(t + 1) * BK * GN);
        }
        #pragma unroll
        for (int kk = 0; kk < BK; kk++) {
            float a_reg[TM], b_reg[TN];
            #pragma unroll
            for (int i = 0; i < TM; i++) a_reg[i] = As[buf][kk][ty * TM + i];
            #pragma unroll
            for (int j = 0; j < TN; j++) b_reg[j] = Bs[buf][kk][tx * TN + j];
            #pragma unroll
            for (int i = 0; i < TM; i++)
                #pragma unroll
                for (int j = 0; j < TN; j++)
                    acc[i][j] = fmaf(a_reg[i], b_reg[j], acc[i][j]);
        }
        if (more) {
            const int nb = buf ^ 1;
            As[nb][a_k + 0][a_row] = av.x;
            As[nb][a_k + 1][a_row] = av.y;
            As[nb][a_k + 2][a_row] = av.z;
            As[nb][a_k + 3][a_row] = av.w;
            *(float4*)&Bs[nb][b_k][b_col] = bv;
            __syncthreads();
            buf = nb;
        }
    }

    // epilogue
    float* Cbase = C + ((size_t)(by * BM)) * GN + bx * BNT;
    #pragma unroll
    for (int i = 0; i < TM; i++) {
        const int row = ty * TM + i;
        #pragma unroll
        for (int j = 0; j < TN; j += 4) {
            const int col = tx * TN + j;
            float4 v;
            v.x = acc[i][j + 0]; v.y = acc[i][j + 1];
            v.z = acc[i][j + 2]; v.w = acc[i][j + 3];
            if (bias) {
                const int gc = bx * BNT + col;
                v.x += bias[gc + 0]; v.y += bias[gc + 1];
                v.z += bias[gc + 2]; v.w += bias[gc + 3];
            }
            if (relu) {
                v.x = fmaxf(v.x, 0.f); v.y = fmaxf(v.y, 0.f);
                v.z = fmaxf(v.z, 0.f); v.w = fmaxf(v.w, 0.f);
            }
            *(float4*)&Cbase[(size_t)row * GN + col] = v;
        }
    }
}

// ---------------- GCN aggregation: 5-point stencil with symmetric norm --------
// out[i] = dinv[i]/deg[i] * sum_{j in nbr(i) U {i}} dinv[j] * x[j]
__device__ __forceinline__ float degf(int r, int c) {
    return 1.f + (float)(c > 0) + (float)(c < GW - 1) + (float)(r > 0) + (float)(r < GH - 1);
}

__global__ void agg_kernel(const float* __restrict__ in, float* __restrict__ out)
{
    const int idx = blockIdx.x * 256 + threadIdx.x;   // [0, 8*4096*128)
    const int c4   = idx & 127;          // channel group (float4)
    const int node = (idx >> 7) & (NNODE - 1);
    const int b    = idx >> 19;
    const int r  = node >> 6;
    const int cc = node & 63;

    const float4* base = (const float4*)in + (size_t)b * NNODE * 128 + c4;
    const float dg  = degf(r, cc);
    const float di  = rsqrtf(dg);

    float4 v = base[(size_t)node * 128];
    float ax = di * v.x, ay = di * v.y, az = di * v.z, aw = di * v.w;

    if (cc > 0) {
        const float dj = rsqrtf(degf(r, cc - 1));
        float4 w = base[(size_t)(node - 1) * 128];
        ax = fmaf(dj, w.x, ax); ay = fmaf(dj, w.y, ay);
        az = fmaf(dj, w.z, az); aw = fmaf(dj, w.w, aw);
    }
    if (cc < GW - 1) {
        const float dj = rsqrtf(degf(r, cc + 1));
        float4 w = base[(size_t)(node + 1) * 128];
        ax = fmaf(dj, w.x, ax); ay = fmaf(dj, w.y, ay);
        az = fmaf(dj, w.z, az); aw = fmaf(dj, w.w, aw);
    }
    if (r > 0) {
        const float dj = rsqrtf(degf(r - 1, cc));
        float4 w = base[(size_t)(node - GW) * 128];
        ax = fmaf(dj, w.x, ax); ay = fmaf(dj, w.y, ay);
        az = fmaf(dj, w.z, az); aw = fmaf(dj, w.w, aw);
    }
    if (r < GH - 1) {
        const float dj = rsqrtf(degf(r + 1, cc));
        float4 w = base[(size_t)(node + GW) * 128];
        ax = fmaf(dj, w.x, ax); ay = fmaf(dj, w.y, ay);
        az = fmaf(dj, w.z, az); aw = fmaf(dj, w.w, aw);
    }

    const float sc = di / dg;
    float4 o;
    o.x = sc * ax; o.y = sc * ay; o.z = sc * az; o.w = sc * aw;
    ((float4*)out)[(size_t)b * NNODE * 128 + (size_t)node * 128 + c4] = o;
}

// ---------------- mean pool partials: 128 blocks (b x slice) ------------------
__global__ void pool_partial_kernel(const float* __restrict__ h2, float* __restrict__ part)
{
    const int b = blockIdx.x;    // 0..7
    const int s = blockIdx.y;    // 0..15
    const int c = threadIdx.x;   // 0..511
    const float* p = h2 + ((size_t)b * NNODE + (size_t)s * 256) * CCH + c;
    float acc = 0.f;
    #pragma unroll 4
    for (int n = 0; n < 256; n++) acc += p[(size_t)n * CCH];
    part[(b * 16 + s) * CCH + c] = acc;
}

// ---------------- BN1 over batch (8 values per channel) -----------------------
__global__ void bn1_kernel(const float* __restrict__ part,
                           const float* __restrict__ g1, const float* __restrict__ beta1,
                           float* __restrict__ xg)
{
    const int c = threadIdx.x;
    float pooled[BATCH];
    float mu = 0.f;
    #pragma unroll
    for (int b = 0; b < BATCH; b++) {
        float s = 0.f;
        #pragma unroll
        for (int k = 0; k < 16; k++) s += part[(b * 16 + k) * CCH + c];
        pooled[b] = s * (1.f / (float)NNODE);
        mu += pooled[b];
    }
    mu *= (1.f / (float)BATCH);
    float var = 0.f;
    #pragma unroll
    for (int b = 0; b < BATCH; b++) { const float d = pooled[b] - mu; var = fmaf(d, d, var); }
    var *= (1.f / (float)BATCH);
    const float inv = rsqrtf(var + EPSV);
    const float ga = g1[c], be = beta1[c];
    #pragma unroll
    for (int b = 0; b < BATCH; b++)
        xg[b * CCH + c] = (pooled[b] - mu) * inv * ga + be;
}

// ---------------- BN2 stats partials over (residual + xg) ---------------------
__global__ void stats_partial_kernel(const float* __restrict__ res,
                                     const float* __restrict__ xg,
                                     float* __restrict__ ps, float* __restrict__ pq)
{
    const int j = blockIdx.x;    // 0..127, 256 rows each
    const int c = threadIdx.x;   // 0..511
    const int row0 = j * 256;
    const int b = row0 >> 12;    // constant within block
    const float xv = xg[b * CCH + c];
    const float* p = res + (size_t)row0 * CCH + c;
    float s = 0.f, q = 0.f;
    #pragma unroll 4
    for (int n = 0; n < 256; n++) {
        const float v = p[(size_t)n * CCH] + xv;
        s += v;
        q = fmaf(v, v, q);
    }
    ps[j * CCH + c] = s;
    pq[j * CCH + c] = q;
}

__global__ void stats_reduce_kernel(const float* __restrict__ ps, const float* __restrict__ pq,
                                    const float* __restrict__ g2, const float* __restrict__ beta2,
                                    float* __restrict__ scale, float* __restrict__ shift)
{
    const int c = threadIdx.x;
    float s = 0.f, q = 0.f;
    #pragma unroll 8
    for (int j = 0; j < 128; j++) { s += ps[j * CCH + c]; q += pq[j * CCH + c]; }
    const float mu  = s * (1.f / (float)MROWS);
    float var = q * (1.f / (float)MROWS) - mu * mu;
    var = fmaxf(var, 0.f);
    const float inv = rsqrtf(var + EPSV);
    const float sc = inv * g2[c];
    scale[c] = sc;
    shift[c] = beta2[c] - mu * sc;
}

// ---------------- final: BN2 apply + [B,N,C] -> [B,C,H*W] transpose ------------
__global__ void final_kernel(const float* __restrict__ res, const float* __restrict__ xg,
                             const float* __restrict__ scale, const float* __restrict__ shift,
                             float* __restrict__ out)
{
    __shared__ float tile[32][33];
    const int b  = blockIdx.z;
    const int n0 = blockIdx.x * 32;
    const int c0 = blockIdx.y * 32;
    const int tx = threadIdx.x;
    const int ty = threadIdx.y;

    #pragma unroll
    for (int k = 0; k < 4; k++) {
        const int n = n0 + ty + k * 8;
        const int c = c0 + tx;
        tile[ty + k * 8][tx] = res[((size_t)b * NNODE + n) * CCH + c] + xg[b * CCH + c];
    }
    __syncthreads();
    #pragma unroll
    for (int k = 0; k < 4; k++) {
        const int c = c0 + ty + k * 8;
        const int n = n0 + tx;
        out[((size_t)b * CCH + c) * NNODE + n] = tile[tx][ty + k * 8] * scale[c] + shift[c];
    }
}

// ---------------- launch ----------------
extern "C" void kernel_launch(void* const* d_in, const int* in_sizes, int n_in,
                              void* d_out, int out_size)
{
    // Map inputs by size & order (robust to whether H/W scalars appear):
    //   16777216 -> x; 262144 (x4) -> w_res, w_pre, w_g1, w_g2;
    //   512 (x7) -> b_pre, b_g1, b_g2, g1, beta1, g2, beta2
    const float* x = nullptr;
    const float* w[4] = {nullptr, nullptr, nullptr, nullptr};
    const float* v[7] = {nullptr, nullptr, nullptr, nullptr, nullptr, nullptr, nullptr};
    int wi = 0, vi = 0;
    for (int i = 0; i < n_in; i++) {
        const int sz = in_sizes[i];
        if (sz == MROWS * CCH) { if (!x) x = (const float*)d_in[i]; }
        else if (sz == CCH * CCH) { if (wi < 4) w[wi++] = (const float*)d_in[i]; }
        else if (sz == CCH) { if (vi < 7) v[vi++] = (const float*)d_in[i]; }
    }
    const float* w_res = w[0]; const float* w_pre = w[1];
    const float* w_g1 = w[2];  const float* w_g2 = w[3];
    const float* b_pre = v[0]; const float* b_g1 = v[1]; const float* b_g2 = v[2];
    const float* g1 = v[3];    const float* beta1 = v[4];
    const float* g2 = v[5];    const float* beta2 = v[6];

    float *p_res, *p_b1, *p_b2, *p_part, *p_xg, *p_ps, *p_pq, *p_sc, *p_sh;
    cudaGetSymbolAddress((void**)&p_res,  g_residual);
    cudaGetSymbolAddress((void**)&p_b1,   g_buf1);
    cudaGetSymbolAddress((void**)&p_b2,   g_buf2);
    cudaGetSymbolAddress((void**)&p_part, g_pool_part);
    cudaGetSymbolAddress((void**)&p_xg,   g_xg);
    cudaGetSymbolAddress((void**)&p_ps,   g_ps);
    cudaGetSymbolAddress((void**)&p_pq,   g_pq);
    cudaGetSymbolAddress((void**)&p_sc,   g_scale);
    cudaGetSymbolAddress((void**)&p_sh,   g_shift);

    float* out = (float*)d_out;

    dim3 ggrid(GN / BNT, MROWS / BM);   // (4, 256)
    const int agg_blocks = (BATCH * NNODE * (CCH / 4)) / 256;  // 16384

    // residual = x @ w_res
    sgemm_kernel<<<ggrid, 256>>>(x, w_res, p_res, nullptr, 0);
    // xr = x @ w_pre + b_pre
    sgemm_kernel<<<ggrid, 256>>>(x, w_pre, p_b1, b_pre, 0);
    // a1 = Agg(xr)
    agg_kernel<<<agg_blocks, 256>>>(p_b1, p_b2);
    // h1 = relu(a1 @ w_g1 + b_g1)
    sgemm_kernel<<<ggrid, 256>>>(p_b2, w_g1, p_b1, b_g1, 1);
    // a2 = Agg(h1)
    agg_kernel<<<agg_blocks, 256>>>(p_b1, p_b2);
    // h2 = relu(a2 @ w_g2 + b_g2)
    sgemm_kernel<<<ggrid, 256>>>(p_b2, w_g2, p_b1, b_g2, 1);
    // pooled partials + BN1 -> xg
    pool_partial_kernel<<<dim3(BATCH, 16), CCH>>>(p_b1, p_part);
    bn1_kernel<<<1, CCH>>>(p_part, g1, beta1, p_xg);
    // BN2 stats over residual + xg
    stats_partial_kernel<<<128, CCH>>>(p_res, p_xg, p_ps, p_pq);
    stats_reduce_kernel<<<1, CCH>>>(p_ps, p_pq, g2, beta2, p_sc, p_sh);
    // apply BN2 + transpose to [B, C, H, W]
    final_kernel<<<dim3(NNODE / 32, CCH / 32, BATCH), dim3(32, 8)>>>(p_res, p_xg, p_sc, p_sh, out);
}

// round 3
// speedup vs baseline: 2.2173x; 2.2173x over previous
#include <cuda_runtime.h>
#include <cuda_bf16.h>
#include <cstdint>
#include <math.h>

#define BATCH 8
#define GH 64
#define GW 64
#define NNODE 4096
#define CCH 512
#define MROWS (BATCH * NNODE)
#define EPSV 1e-5f

// ---------------- scratch ----------------
__device__ float g_res[MROWS * CCH];
__device__ float g_t[MROWS * CCH];
__device__ __nv_bfloat16 g_xh[MROWS * CCH];
__device__ __nv_bfloat16 g_xl[MROWS * CCH];
__device__ __nv_bfloat16 g_ah[MROWS * CCH];
__device__ __nv_bfloat16 g_al[MROWS * CCH];
__device__ __nv_bfloat16 g_wh[4 * CCH * CCH];   // W^T [N,K] hi
__device__ __nv_bfloat16 g_wl[4 * CCH * CCH];   // W^T [N,K] lo
__device__ float g_pool_part[128 * CCH];
__device__ float g_xg[BATCH * CCH];
__device__ float g_ps[128 * CCH];
__device__ float g_pq[128 * CCH];
__device__ float g_scale[CCH];
__device__ float g_shift[CCH];

// ---------------- helpers ----------------
__device__ __forceinline__ uint32_t smem_u32(const void* p) {
    uint32_t a;
    asm("{ .reg .u64 t; cvta.to.shared.u64 t, %1; cvt.u32.u64 %0, t; }" : "=r"(a) : "l"(p));
    return a;
}
__device__ __forceinline__ void ldsm_x4(uint32_t addr, uint32_t* r) {
    asm volatile("ldmatrix.sync.aligned.m8n8.x4.shared.b16 {%0,%1,%2,%3}, [%4];"
                 : "=r"(r[0]), "=r"(r[1]), "=r"(r[2]), "=r"(r[3]) : "r"(addr));
}
__device__ __forceinline__ void mma16816(float* c, const uint32_t* a, const uint32_t* b) {
    asm volatile("mma.sync.aligned.m16n8k16.row.col.f32.bf16.bf16.f32 "
                 "{%0,%1,%2,%3}, {%4,%5,%6,%7}, {%8,%9}, {%0,%1,%2,%3};"
                 : "+f"(c[0]), "+f"(c[1]), "+f"(c[2]), "+f"(c[3])
                 : "r"(a[0]), "r"(a[1]), "r"(a[2]), "r"(a[3]), "r"(b[0]), "r"(b[1]));
}
__device__ __forceinline__ void cp16(uint32_t dst, const void* src) {
    asm volatile("cp.async.cg.shared.global [%0], [%1], 16;" :: "r"(dst), "l"(src) : "memory");
}
#define CP_COMMIT() asm volatile("cp.async.commit_group;" ::: "memory")
#define CP_WAIT(n)  asm volatile("cp.async.wait_group %0;" :: "n"(n) : "memory")

// ---------------- mma.sync split-bf16 GEMM ----------------
// C[32768,512] = (Ah+Al)[M,K] @ W, with W^T stored [N,K] bf16 (hi/lo).
// CTA 128x128, 8 warps (warp tile 64x32), BK=32, double-buffered cp.async.
#define BKC 32
#define ROWB 80u                      // 64B data + 16B pad per row
#define TILEB 10240u                  // 128 rows * 80B
#define STAGEB (4u * TILEB)           // Ah,Al,Bh,Bl
#define GEMM_SMEM (2u * STAGEB)       // 81920

__global__ __launch_bounds__(256)
void gemm_mma(const __nv_bfloat16* __restrict__ Ah, const __nv_bfloat16* __restrict__ Al,
              const __nv_bfloat16* __restrict__ Bh, const __nv_bfloat16* __restrict__ Bl,
              float* __restrict__ C, const float* __restrict__ bias, int relu)
{
    extern __shared__ __align__(128) char smem[];
    const uint32_t sb = smem_u32(smem);
    const int tid = threadIdx.x;
    const int wid = tid >> 5;
    const int lane = tid & 31;
    const int wm = wid & 1;       // 2 M-halves of 64
    const int wn = wid >> 1;      // 4 N-quarters of 32
    const int mtile = blockIdx.y;
    const int ntile = blockIdx.x;

    const __nv_bfloat16* src0 = Ah + (size_t)mtile * 128 * 512;
    const __nv_bfloat16* src1 = Al + (size_t)mtile * 128 * 512;
    const __nv_bfloat16* src2 = Bh + (size_t)ntile * 128 * 512;
    const __nv_bfloat16* src3 = Bl + (size_t)ntile * 128 * 512;

    float acc[4][4][4];
    #pragma unroll
    for (int i = 0; i < 4; i++)
        #pragma unroll
        for (int j = 0; j < 4; j++)
            #pragma unroll
            for (int k = 0; k < 4; k++) acc[i][j][k] = 0.f;

    // ldmatrix lane coordinates
    const int lr = lane & 15;                       // A: row within 16
    const int lk = lane >> 4;                       // A: k half
    const int bn = (lane & 7) + ((lane >> 4) << 3); // B: n within 16
    const int bk = ((lane >> 3) & 1) << 3;          // B: k half

    // stage loader: 2048 x 16B per stage, 8 per thread
    #define LOAD_STAGE(kc, buf) do { \
        const int _kc = (kc); const uint32_t _sbase = sb + (buf) * STAGEB; \
        _Pragma("unroll") \
        for (int p = 0; p < 8; p++) { \
            const int id = p * 256 + tid; \
            const int sel = id >> 9; \
            const int e = id & 511; \
            const int row = e >> 2, ch = e & 3; \
            const uint32_t dst = _sbase + (uint32_t)sel * TILEB + (uint32_t)row * ROWB + (uint32_t)ch * 16u; \
            const __nv_bfloat16* s = (sel == 0 ? src0 : sel == 1 ? src1 : sel == 2 ? src2 : src3) \
                                     + (size_t)row * 512 + (size_t)_kc * BKC + ch * 8; \
            cp16(dst, s); \
        } \
        CP_COMMIT(); \
    } while (0)

    LOAD_STAGE(0, 0);

    int buf = 0;
    #pragma unroll 1
    for (int kc = 0; kc < 16; kc++) {
        if (kc + 1 < 16) {
            LOAD_STAGE(kc + 1, buf ^ 1);
            CP_WAIT(1);
        } else {
            CP_WAIT(0);
        }
        __syncthreads();

        const uint32_t base = sb + (uint32_t)buf * STAGEB;
        #pragma unroll
        for (int ks = 0; ks < 2; ks++) {
            uint32_t ah[4][4], al[4][4];
            #pragma unroll
            for (int mi = 0; mi < 4; mi++) {
                const uint32_t off = (uint32_t)(wm * 64 + mi * 16 + lr) * ROWB
                                   + (uint32_t)(ks * 16 + lk * 8) * 2u;
                ldsm_x4(base + off, ah[mi]);
                ldsm_x4(base + TILEB + off, al[mi]);
            }
            uint32_t bh[4][2], bl[4][2];
            #pragma unroll
            for (int np = 0; np < 2; np++) {
                const uint32_t off = (uint32_t)(wn * 32 + np * 16 + bn) * ROWB
                                   + (uint32_t)(ks * 16 + bk) * 2u;
                uint32_t r[4];
                ldsm_x4(base + 2u * TILEB + off, r);
                bh[np * 2][0] = r[0]; bh[np * 2][1] = r[1];
                bh[np * 2 + 1][0] = r[2]; bh[np * 2 + 1][1] = r[3];
                ldsm_x4(base + 3u * TILEB + off, r);
                bl[np * 2][0] = r[0]; bl[np * 2][1] = r[1];
                bl[np * 2 + 1][0] = r[2]; bl[np * 2 + 1][1] = r[3];
            }
            #pragma unroll
            for (int mi = 0; mi < 4; mi++)
                #pragma unroll
                for (int nb = 0; nb < 4; nb++) {
                    mma16816(acc[mi][nb], ah[mi], bh[nb]);
                    mma16816(acc[mi][nb], ah[mi], bl[nb]);
                    mma16816(acc[mi][nb], al[mi], bh[nb]);
                }
        }
        __syncthreads();
        buf ^= 1;
    }

    // epilogue
    const int gid = lane >> 2;
    const int tig = lane & 3;
    #pragma unroll
    for (int mi = 0; mi < 4; mi++) {
        const int row0 = mtile * 128 + wm * 64 + mi * 16 + gid;
        #pragma unroll
        for (int nb = 0; nb < 4; nb++) {
            const int col = ntile * 128 + wn * 32 + nb * 8 + tig * 2;
            float b0 = 0.f, b1 = 0.f;
            if (bias) { b0 = bias[col]; b1 = bias[col + 1]; }
            float2 v0, v1;
            v0.x = acc[mi][nb][0] + b0; v0.y = acc[mi][nb][1] + b1;
            v1.x = acc[mi][nb][2] + b0; v1.y = acc[mi][nb][3] + b1;
            if (relu) {
                v0.x = fmaxf(v0.x, 0.f); v0.y = fmaxf(v0.y, 0.f);
                v1.x = fmaxf(v1.x, 0.f); v1.y = fmaxf(v1.y, 0.f);
            }
            *(float2*)(C + (size_t)row0 * 512 + col) = v0;
            *(float2*)(C + (size_t)(row0 + 8) * 512 + col) = v1;
        }
    }
}

// ---------------- fp32 -> bf16 hi/lo split ----------------
__device__ __forceinline__ void split4(float4 v, ushort4& h, ushort4& l) {
    __nv_bfloat16 b;
    b = __float2bfloat16(v.x); h.x = __bfloat16_as_ushort(b); l.x = __bfloat16_as_ushort(__float2bfloat16(v.x - __bfloat162float(b)));
    b = __float2bfloat16(v.y); h.y = __bfloat16_as_ushort(b); l.y = __bfloat16_as_ushort(__float2bfloat16(v.y - __bfloat162float(b)));
    b = __float2bfloat16(v.z); h.z = __bfloat16_as_ushort(b); l.z = __bfloat16_as_ushort(__float2bfloat16(v.z - __bfloat162float(b)));
    b = __float2bfloat16(v.w); h.w = __bfloat16_as_ushort(b); l.w = __bfloat16_as_ushort(__float2bfloat16(v.w - __bfloat162float(b)));
}

__global__ void convert_x_kernel(const float* __restrict__ x,
                                 __nv_bfloat16* __restrict__ xh, __nv_bfloat16* __restrict__ xl)
{
    const size_t i = ((size_t)blockIdx.x * 256 + threadIdx.x) * 4;
    float4 v = *(const float4*)(x + i);
    ushort4 h, l;
    split4(v, h, l);
    *(ushort4*)(xh + i) = h;
    *(ushort4*)(xl + i) = l;
}

__global__ void convert_w_kernel(const float* __restrict__ w,
                                 __nv_bfloat16* __restrict__ wh, __nv_bfloat16* __restrict__ wl)
{
    __shared__ float t[32][33];
    const int n0 = blockIdx.x * 32;
    const int k0 = blockIdx.y * 32;
    const int tx = threadIdx.x, ty = threadIdx.y;
    #pragma unroll
    for (int j = 0; j < 4; j++)
        t[ty + j * 8][tx] = w[(size_t)(k0 + ty + j * 8) * 512 + n0 + tx];
    __syncthreads();
    #pragma unroll
    for (int j = 0; j < 4; j++) {
        const float v = t[tx][ty + j * 8];
        const __nv_bfloat16 hb = __float2bfloat16(v);
        wh[(size_t)(n0 + ty + j * 8) * 512 + k0 + tx] = hb;
        wl[(size_t)(n0 + ty + j * 8) * 512 + k0 + tx] = __float2bfloat16(v - __bfloat162float(hb));
    }
}

// ---------------- GCN aggregation (fp32 in -> bf16 hi/lo out) ----------------
__device__ __forceinline__ float degf(int r, int c) {
    return 1.f + (float)(c > 0) + (float)(c < GW - 1) + (float)(r > 0) + (float)(r < GH - 1);
}

__global__ void agg_split_kernel(const float* __restrict__ in,
                                 __nv_bfloat16* __restrict__ oh, __nv_bfloat16* __restrict__ ol)
{
    const int idx = blockIdx.x * 256 + threadIdx.x;
    const int c4 = idx & 127;
    const int node = (idx >> 7) & (NNODE - 1);
    const int b = idx >> 19;
    const int r = node >> 6;
    const int cc = node & 63;

    const float4* base = (const float4*)in + (size_t)b * NNODE * 128 + c4;
    const float dg = degf(r, cc);
    const float di = rsqrtf(dg);

    float4 v = base[(size_t)node * 128];
    float ax = di * v.x, ay = di * v.y, az = di * v.z, aw = di * v.w;
    if (cc > 0) {
        const float dj = rsqrtf(degf(r, cc - 1));
        float4 w = base[(size_t)(node - 1) * 128];
        ax = fmaf(dj, w.x, ax); ay = fmaf(dj, w.y, ay); az = fmaf(dj, w.z, az); aw = fmaf(dj, w.w, aw);
    }
    if (cc < GW - 1) {
        const float dj = rsqrtf(degf(r, cc + 1));
        float4 w = base[(size_t)(node + 1) * 128];
        ax = fmaf(dj, w.x, ax); ay = fmaf(dj, w.y, ay); az = fmaf(dj, w.z, az); aw = fmaf(dj, w.w, aw);
    }
    if (r > 0) {
        const float dj = rsqrtf(degf(r - 1, cc));
        float4 w = base[(size_t)(node - GW) * 128];
        ax = fmaf(dj, w.x, ax); ay = fmaf(dj, w.y, ay); az = fmaf(dj, w.z, az); aw = fmaf(dj, w.w, aw);
    }
    if (r < GH - 1) {
        const float dj = rsqrtf(degf(r + 1, cc));
        float4 w = base[(size_t)(node + GW) * 128];
        ax = fmaf(dj, w.x, ax); ay = fmaf(dj, w.y, ay); az = fmaf(dj, w.z, az); aw = fmaf(dj, w.w, aw);
    }
    const float sc = di / dg;
    float4 o;
    o.x = sc * ax; o.y = sc * ay; o.z = sc * az; o.w = sc * aw;
    ushort4 h, l;
    split4(o, h, l);
    const size_t e = (size_t)b * NNODE * CCH + (size_t)node * CCH + c4 * 4;
    *(ushort4*)(oh + e) = h;
    *(ushort4*)(ol + e) = l;
}

// ---------------- tail ----------------
__global__ void pool_partial_kernel(const float* __restrict__ h2, float* __restrict__ part)
{
    const int b = blockIdx.x, s = blockIdx.y, c = threadIdx.x;
    const float* p = h2 + ((size_t)b * NNODE + (size_t)s * 256) * CCH + c;
    float acc = 0.f;
    #pragma unroll 4
    for (int n = 0; n < 256; n++) acc += p[(size_t)n * CCH];
    part[(b * 16 + s) * CCH + c] = acc;
}

__global__ void bn1_kernel(const float* __restrict__ part,
                           const float* __restrict__ g1, const float* __restrict__ beta1,
                           float* __restrict__ xg)
{
    const int c = threadIdx.x;
    float pooled[BATCH];
    float mu = 0.f;
    #pragma unroll
    for (int b = 0; b < BATCH; b++) {
        float s = 0.f;
        #pragma unroll
        for (int k = 0; k < 16; k++) s += part[(b * 16 + k) * CCH + c];
        pooled[b] = s * (1.f / (float)NNODE);
        mu += pooled[b];
    }
    mu *= (1.f / (float)BATCH);
    float var = 0.f;
    #pragma unroll
    for (int b = 0; b < BATCH; b++) { const float d = pooled[b] - mu; var = fmaf(d, d, var); }
    var *= (1.f / (float)BATCH);
    const float inv = rsqrtf(var + EPSV);
    const float ga = g1[c], be = beta1[c];
    #pragma unroll
    for (int b = 0; b < BATCH; b++)
        xg[b * CCH + c] = (pooled[b] - mu) * inv * ga + be;
}

__global__ void stats_partial_kernel(const float* __restrict__ res, const float* __restrict__ xg,
                                     float* __restrict__ ps, float* __restrict__ pq)
{
    const int j = blockIdx.x, c = threadIdx.x;
    const int row0 = j * 256;
    const int b = row0 >> 12;
    const float xv = xg[b * CCH + c];
    const float* p = res + (size_t)row0 * CCH + c;
    float s = 0.f, q = 0.f;
    #pragma unroll 4
    for (int n = 0; n < 256; n++) {
        const float v = p[(size_t)n * CCH] + xv;
        s += v; q = fmaf(v, v, q);
    }
    ps[j * CCH + c] = s;
    pq[j * CCH + c] = q;
}

__global__ void stats_reduce_kernel(const float* __restrict__ ps, const float* __restrict__ pq,
                                    const float* __restrict__ g2, const float* __restrict__ beta2,
                                    float* __restrict__ scale, float* __restrict__ shift)
{
    const int c = threadIdx.x;
    float s = 0.f, q = 0.f;
    #pragma unroll 8
    for (int j = 0; j < 128; j++) { s += ps[j * CCH + c]; q += pq[j * CCH + c]; }
    const float mu = s * (1.f / (float)MROWS);
    float var = q * (1.f / (float)MROWS) - mu * mu;
    var = fmaxf(var, 0.f);
    const float inv = rsqrtf(var + EPSV);
    const float sc = inv * g2[c];
    scale[c] = sc;
    shift[c] = beta2[c] - mu * sc;
}

__global__ void final_kernel(const float* __restrict__ res, const float* __restrict__ xg,
                             const float* __restrict__ scale, const float* __restrict__ shift,
                             float* __restrict__ out)
{
    __shared__ float tile[32][33];
    const int b = blockIdx.z;
    const int n0 = blockIdx.x * 32;
    const int c0 = blockIdx.y * 32;
    const int tx = threadIdx.x, ty = threadIdx.y;
    #pragma unroll
    for (int k = 0; k < 4; k++) {
        const int n = n0 + ty + k * 8;
        const int c = c0 + tx;
        tile[ty + k * 8][tx] = res[((size_t)b * NNODE + n) * CCH + c] + xg[b * CCH + c];
    }
    __syncthreads();
    #pragma unroll
    for (int k = 0; k < 4; k++) {
        const int c = c0 + ty + k * 8;
        const int n = n0 + tx;
        out[((size_t)b * CCH + c) * NNODE + n] = tile[tx][ty + k * 8] * scale[c] + shift[c];
    }
}

// ---------------- launch ----------------
extern "C" void kernel_launch(void* const* d_in, const int* in_sizes, int n_in,
                              void* d_out, int out_size)
{
    const float* x = nullptr;
    const float* w[4] = {nullptr, nullptr, nullptr, nullptr};
    const float* v[7] = {nullptr, nullptr, nullptr, nullptr, nullptr, nullptr, nullptr};
    int wi = 0, vi = 0;
    for (int i = 0; i < n_in; i++) {
        const int sz = in_sizes[i];
        if (sz == MROWS * CCH) { if (!x) x = (const float*)d_in[i]; }
        else if (sz == CCH * CCH) { if (wi < 4) w[wi++] = (const float*)d_in[i]; }
        else if (sz == CCH) { if (vi < 7) v[vi++] = (const float*)d_in[i]; }
    }
    const float* b_pre = v[0]; const float* b_g1 = v[1]; const float* b_g2 = v[2];
    const float* g1 = v[3];    const float* beta1 = v[4];
    const float* g2 = v[5];    const float* beta2 = v[6];

    float *p_res, *p_t, *p_part, *p_xg, *p_ps, *p_pq, *p_sc, *p_sh;
    __nv_bfloat16 *p_xh, *p_xl, *p_ah, *p_al, *p_wh, *p_wl;
    cudaGetSymbolAddress((void**)&p_res, g_res);
    cudaGetSymbolAddress((void**)&p_t, g_t);
    cudaGetSymbolAddress((void**)&p_xh, g_xh);
    cudaGetSymbolAddress((void**)&p_xl, g_xl);
    cudaGetSymbolAddress((void**)&p_ah, g_ah);
    cudaGetSymbolAddress((void**)&p_al, g_al);
    cudaGetSymbolAddress((void**)&p_wh, g_wh);
    cudaGetSymbolAddress((void**)&p_wl, g_wl);
    cudaGetSymbolAddress((void**)&p_part, g_pool_part);
    cudaGetSymbolAddress((void**)&p_xg, g_xg);
    cudaGetSymbolAddress((void**)&p_ps, g_ps);
    cudaGetSymbolAddress((void**)&p_pq, g_pq);
    cudaGetSymbolAddress((void**)&p_sc, g_scale);
    cudaGetSymbolAddress((void**)&p_sh, g_shift);

    float* out = (float*)d_out;

    cudaFuncSetAttribute(gemm_mma, cudaFuncAttributeMaxDynamicSharedMemorySize, (int)GEMM_SMEM);

    const dim3 ggrid(4, 256);   // N tiles x M tiles
    const int agg_blocks = (BATCH * NNODE * (CCH / 4)) / 256;
    const dim3 wgrid(16, 16), wthr(32, 8);

    convert_x_kernel<<<(MROWS * CCH / 4) / 256, 256>>>(x, p_xh, p_xl);
    for (int i = 0; i < 4; i++)
        convert_w_kernel<<<wgrid, wthr>>>(w[i], p_wh + (size_t)i * CCH * CCH, p_wl + (size_t)i * CCH * CCH);

    // residual = x @ w_res
    gemm_mma<<<ggrid, 256, GEMM_SMEM>>>(p_xh, p_xl, p_wh, p_wl, p_res, nullptr, 0);
    // xr = x @ w_pre + b_pre
    gemm_mma<<<ggrid, 256, GEMM_SMEM>>>(p_xh, p_xl, p_wh + (size_t)1 * CCH * CCH, p_wl + (size_t)1 * CCH * CCH, p_t, b_pre, 0);
    // a1 = Agg(xr)
    agg_split_kernel<<<agg_blocks, 256>>>(p_t, p_ah, p_al);
    // h1 = relu(a1 @ w_g1 + b_g1)
    gemm_mma<<<ggrid, 256, GEMM_SMEM>>>(p_ah, p_al, p_wh + (size_t)2 * CCH * CCH, p_wl + (size_t)2 * CCH * CCH, p_t, b_g1, 1);
    // a2 = Agg(h1)
    agg_split_kernel<<<agg_blocks, 256>>>(p_t, p_ah, p_al);
    // h2 = relu(a2 @ w_g2 + b_g2)
    gemm_mma<<<ggrid, 256, GEMM_SMEM>>>(p_ah, p_al, p_wh + (size_t)3 * CCH * CCH, p_wl + (size_t)3 * CCH * CCH, p_t, b_g2, 1);

    // tail
    pool_partial_kernel<<<dim3(BATCH, 16), CCH>>>(p_t, p_part);
    bn1_kernel<<<1, CCH>>>(p_part, g1, beta1, p_xg);
    stats_partial_kernel<<<128, CCH>>>(p_res, p_xg, p_ps, p_pq);
    stats_reduce_kernel<<<1, CCH>>>(p_ps, p_pq, g2, beta2, p_sc, p_sh);
    final_kernel<<<dim3(NNODE / 32, CCH / 32, BATCH), dim3(32, 8)>>>(p_res, p_xg, p_sc, p_sh, out);
}

// round 4
// speedup vs baseline: 2.4113x; 1.0875x over previous
#include <cuda_runtime.h>
#include <cuda_bf16.h>
#include <cstdint>
#include <math.h>

#define BATCH 8
#define GH 64
#define GW 64
#define NNODE 4096
#define CCH 512
#define MROWS (BATCH * NNODE)
#define EPSV 1e-5f

// ---------------- scratch ----------------
__device__ float g_res[MROWS * CCH];
__device__ float g_t[MROWS * CCH];
__device__ __nv_bfloat16 g_xh[MROWS * CCH];
__device__ __nv_bfloat16 g_xl[MROWS * CCH];
__device__ __nv_bfloat16 g_ah[MROWS * CCH];
__device__ __nv_bfloat16 g_al[MROWS * CCH];
__device__ __nv_bfloat16 g_wh[4 * CCH * CCH];   // W^T [N,K] hi, 4 contiguous blocks
__device__ __nv_bfloat16 g_wl[4 * CCH * CCH];   // W^T [N,K] lo
__device__ float g_hp[256 * CCH];               // h2 column-sum partials per mtile
__device__ float g_rs[256 * CCH];               // res column-sum partials per mtile
__device__ float g_rq[256 * CCH];               // res column-sumsq partials per mtile
__device__ float g_xg[BATCH * CCH];
__device__ float g_scale[CCH];
__device__ float g_shift[CCH];

// ---------------- helpers ----------------
__device__ __forceinline__ uint32_t smem_u32(const void* p) {
    uint32_t a;
    asm("{ .reg .u64 t; cvta.to.shared.u64 t, %1; cvt.u32.u64 %0, t; }" : "=r"(a) : "l"(p));
    return a;
}
__device__ __forceinline__ void ldsm_x4(uint32_t addr, uint32_t* r) {
    asm volatile("ldmatrix.sync.aligned.m8n8.x4.shared.b16 {%0,%1,%2,%3}, [%4];"
                 : "=r"(r[0]), "=r"(r[1]), "=r"(r[2]), "=r"(r[3]) : "r"(addr));
}
__device__ __forceinline__ void mma16816(float* c, const uint32_t* a, const uint32_t* b) {
    asm volatile("mma.sync.aligned.m16n8k16.row.col.f32.bf16.bf16.f32 "
                 "{%0,%1,%2,%3}, {%4,%5,%6,%7}, {%8,%9}, {%0,%1,%2,%3};"
                 : "+f"(c[0]), "+f"(c[1]), "+f"(c[2]), "+f"(c[3])
                 : "r"(a[0]), "r"(a[1]), "r"(a[2]), "r"(a[3]), "r"(b[0]), "r"(b[1]));
}
__device__ __forceinline__ void cp16(uint32_t dst, const void* src) {
    asm volatile("cp.async.cg.shared.global [%0], [%1], 16;" :: "r"(dst), "l"(src) : "memory");
}
#define CP_COMMIT() asm volatile("cp.async.commit_group;" ::: "memory")
#define CP_WAIT0()  asm volatile("cp.async.wait_group 0;" ::: "memory")

// ---------------- mma.sync split-bf16 GEMM with fused epilogue reductions ------
// mode bits: 1=store C, 2=relu, 4=bias, 8=column-sum partials, 16=also sumsq
#define BKC 32
#define ROWB 80u
#define TILEB 10240u
#define STAGEB (4u * TILEB)
#define GEMM_SMEM (2u * STAGEB)

__global__ __launch_bounds__(256, 2)
void gemm_mma(const __nv_bfloat16* __restrict__ Ah, const __nv_bfloat16* __restrict__ Al,
              const __nv_bfloat16* __restrict__ Bh, const __nv_bfloat16* __restrict__ Bl,
              float* __restrict__ C0, float* __restrict__ C1,
              const float* __restrict__ bias0, const float* __restrict__ bias1,
              float* __restrict__ redS, float* __restrict__ redQ,
              int mode0, int mode1)
{
    extern __shared__ __align__(128) char smem[];
    const uint32_t sb = smem_u32(smem);
    const int tid = threadIdx.x;
    const int wid = tid >> 5;
    const int lane = tid & 31;
    const int wm = wid & 1;
    const int wn = wid >> 1;
    const int mtile = blockIdx.y;
    const int ntile = blockIdx.x;

    const __nv_bfloat16* src0 = Ah + (size_t)mtile * 128 * 512;
    const __nv_bfloat16* src1 = Al + (size_t)mtile * 128 * 512;
    const __nv_bfloat16* src2 = Bh + (size_t)ntile * 128 * 512;
    const __nv_bfloat16* src3 = Bl + (size_t)ntile * 128 * 512;

    float acc[4][4][4];
    #pragma unroll
    for (int i = 0; i < 4; i++)
        #pragma unroll
        for (int j = 0; j < 4; j++)
            #pragma unroll
            for (int k = 0; k < 4; k++) acc[i][j][k] = 0.f;

    const int lr = lane & 15;
    const int lk = lane >> 4;
    const int bn = (lane & 7) + ((lane >> 4) << 3);
    const int bk = ((lane >> 3) & 1) << 3;

    #define LOAD_STAGE(kc, buf) do { \
        const int _kc = (kc); const uint32_t _sbase = sb + (buf) * STAGEB; \
        _Pragma("unroll") \
        for (int p = 0; p < 8; p++) { \
            const int id = p * 256 + tid; \
            const int sel = id >> 9; \
            const int e = id & 511; \
            const int row = e >> 2, ch = e & 3; \
            const uint32_t dst = _sbase + (uint32_t)sel * TILEB + (uint32_t)row * ROWB + (uint32_t)ch * 16u; \
            const __nv_bfloat16* s = (sel == 0 ? src0 : sel == 1 ? src1 : sel == 2 ? src2 : src3) \
                                     + (size_t)row * 512 + (size_t)_kc * BKC + ch * 8; \
            cp16(dst, s); \
        } \
        CP_COMMIT(); \
    } while (0)

    LOAD_STAGE(0, 0);

    int buf = 0;
    #pragma unroll 1
    for (int kc = 0; kc < 16; kc++) {
        CP_WAIT0();            // stage kc landed
        __syncthreads();       // all warps done with stage kc-1 (same buffer as kc+1)
        if (kc + 1 < 16) LOAD_STAGE(kc + 1, buf ^ 1);

        const uint32_t base = sb + (uint32_t)buf * STAGEB;
        #pragma unroll
        for (int ks = 0; ks < 2; ks++) {
            uint32_t ah[4][4], al[4][4];
            #pragma unroll
            for (int mi = 0; mi < 4; mi++) {
                const uint32_t off = (uint32_t)(wm * 64 + mi * 16 + lr) * ROWB
                                   + (uint32_t)(ks * 16 + lk * 8) * 2u;
                ldsm_x4(base + off, ah[mi]);
                ldsm_x4(base + TILEB + off, al[mi]);
            }
            uint32_t bh[4][2], bl[4][2];
            #pragma unroll
            for (int np = 0; np < 2; np++) {
                const uint32_t off = (uint32_t)(wn * 32 + np * 16 + bn) * ROWB
                                   + (uint32_t)(ks * 16 + bk) * 2u;
                uint32_t r[4];
                ldsm_x4(base + 2u * TILEB + off, r);
                bh[np * 2][0] = r[0]; bh[np * 2][1] = r[1];
                bh[np * 2 + 1][0] = r[2]; bh[np * 2 + 1][1] = r[3];
                ldsm_x4(base + 3u * TILEB + off, r);
                bl[np * 2][0] = r[0]; bl[np * 2][1] = r[1];
                bl[np * 2 + 1][0] = r[2]; bl[np * 2 + 1][1] = r[3];
            }
            #pragma unroll
            for (int mi = 0; mi < 4; mi++)
                #pragma unroll
                for (int nb = 0; nb < 4; nb++) {
                    mma16816(acc[mi][nb], ah[mi], bh[nb]);
                    mma16816(acc[mi][nb], ah[mi], bl[nb]);
                    mma16816(acc[mi][nb], al[mi], bh[nb]);
                }
        }
        buf ^= 1;
    }

    // ---------------- epilogue ----------------
    const int selc = ntile >> 2;   // grid.x=8 dual: 0..3 -> out0, 4..7 -> out1
    const int mode = selc ? mode1 : mode0;
    const float* bias = selc ? bias1 : bias0;
    float* C = selc ? C1 : C0;
    const int ncol = (ntile & 3) * 128;

    const int gid = lane >> 2;
    const int tig = lane & 3;

    float rsum[4][2], rq[4][2];
    #pragma unroll
    for (int nb = 0; nb < 4; nb++) { rsum[nb][0] = rsum[nb][1] = rq[nb][0] = rq[nb][1] = 0.f; }

    #pragma unroll
    for (int mi = 0; mi < 4; mi++) {
        const int row0 = mtile * 128 + wm * 64 + mi * 16 + gid;
        #pragma unroll
        for (int nb = 0; nb < 4; nb++) {
            const int col = ncol + wn * 32 + nb * 8 + tig * 2;
            float b0 = 0.f, b1 = 0.f;
            if (mode & 4) { b0 = __ldg(bias + col); b1 = __ldg(bias + col + 1); }
            float v0 = acc[mi][nb][0] + b0, v1 = acc[mi][nb][1] + b1;
            float v2 = acc[mi][nb][2] + b0, v3 = acc[mi][nb][3] + b1;
            if (mode & 2) {
                v0 = fmaxf(v0, 0.f); v1 = fmaxf(v1, 0.f);
                v2 = fmaxf(v2, 0.f); v3 = fmaxf(v3, 0.f);
            }
            if (mode & 1) {
                float2 w0 = make_float2(v0, v1), w1 = make_float2(v2, v3);
                *(float2*)(C + (size_t)row0 * 512 + col) = w0;
                *(float2*)(C + (size_t)(row0 + 8) * 512 + col) = w1;
            }
            if (mode & 8) {
                rsum[nb][0] += v0 + v2; rsum[nb][1] += v1 + v3;
                if (mode & 16) {
                    rq[nb][0] = fmaf(v0, v0, fmaf(v2, v2, rq[nb][0]));
                    rq[nb][1] = fmaf(v1, v1, fmaf(v3, v3, rq[nb][1]));
                }
            }
        }
    }

    if (mode & 8) {
        // reduce over gid (8 row-lanes): lanes gid*4+tig; xor masks 4,8,16
        #pragma unroll
        for (int nb = 0; nb < 4; nb++)
            #pragma unroll
            for (int j = 0; j < 2; j++) {
                #pragma unroll
                for (int m = 4; m <= 16; m <<= 1) {
                    rsum[nb][j] += __shfl_xor_sync(0xffffffffu, rsum[nb][j], m);
                    rq[nb][j]   += __shfl_xor_sync(0xffffffffu, rq[nb][j], m);
                }
            }
        __syncthreads();   // stages dead; reuse smem for cross-warp reduce
        float* red = (float*)smem;   // [2:{sum,sq}][2:wm][128]
        if (gid == 0) {
            #pragma unroll
            for (int nb = 0; nb < 4; nb++) {
                const int c = wn * 32 + nb * 8 + tig * 2;
                red[wm * 128 + c]     = rsum[nb][0];
                red[wm * 128 + c + 1] = rsum[nb][1];
                red[256 + wm * 128 + c]     = rq[nb][0];
                red[256 + wm * 128 + c + 1] = rq[nb][1];
            }
        }
        __syncthreads();
        if (tid < 128) {
            const float s = red[tid] + red[128 + tid];
            redS[(size_t)mtile * 512 + ncol + tid] = s;
            if (mode & 16) {
                const float q = red[256 + tid] + red[384 + tid];
                redQ[(size_t)mtile * 512 + ncol + tid] = q;
            }
        }
    }
}

// ---------------- fp32 -> bf16 hi/lo split ----------------
__device__ __forceinline__ void split4(float4 v, ushort4& h, ushort4& l) {
    __nv_bfloat16 b;
    b = __float2bfloat16(v.x); h.x = __bfloat16_as_ushort(b); l.x = __bfloat16_as_ushort(__float2bfloat16(v.x - __bfloat162float(b)));
    b = __float2bfloat16(v.y); h.y = __bfloat16_as_ushort(b); l.y = __bfloat16_as_ushort(__float2bfloat16(v.y - __bfloat162float(b)));
    b = __float2bfloat16(v.z); h.z = __bfloat16_as_ushort(b); l.z = __bfloat16_as_ushort(__float2bfloat16(v.z - __bfloat162float(b)));
    b = __float2bfloat16(v.w); h.w = __bfloat16_as_ushort(b); l.w = __bfloat16_as_ushort(__float2bfloat16(v.w - __bfloat162float(b)));
}

__global__ void convert_x_kernel(const float* __restrict__ x,
                                 __nv_bfloat16* __restrict__ xh, __nv_bfloat16* __restrict__ xl)
{
    const size_t i = ((size_t)blockIdx.x * 256 + threadIdx.x) * 4;
    float4 v = *(const float4*)(x + i);
    ushort4 h, l;
    split4(v, h, l);
    *(ushort4*)(xh + i) = h;
    *(ushort4*)(xl + i) = l;
}

__global__ void convert_w_kernel(const float* __restrict__ w,
                                 __nv_bfloat16* __restrict__ wh, __nv_bfloat16* __restrict__ wl)
{
    __shared__ float t[32][33];
    const int n0 = blockIdx.x * 32;
    const int k0 = blockIdx.y * 32;
    const int tx = threadIdx.x, ty = threadIdx.y;
    #pragma unroll
    for (int j = 0; j < 4; j++)
        t[ty + j * 8][tx] = w[(size_t)(k0 + ty + j * 8) * 512 + n0 + tx];
    __syncthreads();
    #pragma unroll
    for (int j = 0; j < 4; j++) {
        const float v = t[tx][ty + j * 8];
        const __nv_bfloat16 hb = __float2bfloat16(v);
        wh[(size_t)(n0 + ty + j * 8) * 512 + k0 + tx] = hb;
        wl[(size_t)(n0 + ty + j * 8) * 512 + k0 + tx] = __float2bfloat16(v - __bfloat162float(hb));
    }
}

// ---------------- GCN aggregation (fp32 in -> bf16 hi/lo out) ----------------
__device__ __forceinline__ float degf(int r, int c) {
    return 1.f + (float)(c > 0) + (float)(c < GW - 1) + (float)(r > 0) + (float)(r < GH - 1);
}

__global__ void agg_split_kernel(const float* __restrict__ in,
                                 __nv_bfloat16* __restrict__ oh, __nv_bfloat16* __restrict__ ol)
{
    const int idx = blockIdx.x * 256 + threadIdx.x;
    const int c4 = idx & 127;
    const int node = (idx >> 7) & (NNODE - 1);
    const int b = idx >> 19;
    const int r = node >> 6;
    const int cc = node & 63;

    const float4* base = (const float4*)in + (size_t)b * NNODE * 128 + c4;
    const float dg = degf(r, cc);
    const float di = rsqrtf(dg);

    float4 v = base[(size_t)node * 128];
    float ax = di * v.x, ay = di * v.y, az = di * v.z, aw = di * v.w;
    if (cc > 0) {
        const float dj = rsqrtf(degf(r, cc - 1));
        float4 w = base[(size_t)(node - 1) * 128];
        ax = fmaf(dj, w.x, ax); ay = fmaf(dj, w.y, ay); az = fmaf(dj, w.z, az); aw = fmaf(dj, w.w, aw);
    }
    if (cc < GW - 1) {
        const float dj = rsqrtf(degf(r, cc + 1));
        float4 w = base[(size_t)(node + 1) * 128];
        ax = fmaf(dj, w.x, ax); ay = fmaf(dj, w.y, ay); az = fmaf(dj, w.z, az); aw = fmaf(dj, w.w, aw);
    }
    if (r > 0) {
        const float dj = rsqrtf(degf(r - 1, cc));
        float4 w = base[(size_t)(node - GW) * 128];
        ax = fmaf(dj, w.x, ax); ay = fmaf(dj, w.y, ay); az = fmaf(dj, w.z, az); aw = fmaf(dj, w.w, aw);
    }
    if (r < GH - 1) {
        const float dj = rsqrtf(degf(r + 1, cc));
        float4 w = base[(size_t)(node + GW) * 128];
        ax = fmaf(dj, w.x, ax); ay = fmaf(dj, w.y, ay); az = fmaf(dj, w.z, az); aw = fmaf(dj, w.w, aw);
    }
    const float sc = di / dg;
    float4 o;
    o.x = sc * ax; o.y = sc * ay; o.z = sc * az; o.w = sc * aw;
    ushort4 h, l;
    split4(o, h, l);
    const size_t e = (size_t)b * NNODE * CCH + (size_t)node * CCH + c4 * 4;
    *(ushort4*)(oh + e) = h;
    *(ushort4*)(ol + e) = l;
}

// ---------------- BN1 from fused h2 partials ----------------
__global__ void bn1_kernel(const float* __restrict__ hp,
                           const float* __restrict__ g1, const float* __restrict__ beta1,
                           float* __restrict__ xg)
{
    const int c = threadIdx.x;
    float pooled[BATCH];
    float mu = 0.f;
    #pragma unroll
    for (int b = 0; b < BATCH; b++) {
        float s = 0.f;
        #pragma unroll 8
        for (int k = 0; k < 32; k++) s += hp[(size_t)(b * 32 + k) * CCH + c];
        pooled[b] = s * (1.f / (float)NNODE);
        mu += pooled[b];
    }
    mu *= (1.f / (float)BATCH);
    float var = 0.f;
    #pragma unroll
    for (int b = 0; b < BATCH; b++) { const float d = pooled[b] - mu; var = fmaf(d, d, var); }
    var *= (1.f / (float)BATCH);
    const float inv = rsqrtf(var + EPSV);
    const float ga = g1[c], be = beta1[c];
    #pragma unroll
    for (int b = 0; b < BATCH; b++)
        xg[b * CCH + c] = (pooled[b] - mu) * inv * ga + be;
}

// ---------------- BN2 scale/shift from fused res partials + xg ----------------
__global__ void stats_reduce_kernel(const float* __restrict__ rs, const float* __restrict__ rq,
                                    const float* __restrict__ xg,
                                    const float* __restrict__ g2, const float* __restrict__ beta2,
                                    float* __restrict__ scale, float* __restrict__ shift)
{
    const int c = threadIdx.x;
    float S = 0.f, Q = 0.f;
    #pragma unroll
    for (int b = 0; b < BATCH; b++) {
        float sb = 0.f, qb = 0.f;
        #pragma unroll 8
        for (int k = 0; k < 32; k++) {
            const size_t idx = (size_t)(b * 32 + k) * CCH + c;
            sb += rs[idx]; qb += rq[idx];
        }
        const float xv = xg[b * CCH + c];
        S += sb + 4096.f * xv;
        Q += qb + 2.f * xv * sb + 4096.f * xv * xv;
    }
    const float mu = S * (1.f / (float)MROWS);
    float var = Q * (1.f / (float)MROWS) - mu * mu;
    var = fmaxf(var, 0.f);
    const float inv = rsqrtf(var + EPSV);
    const float sc = inv * g2[c];
    scale[c] = sc;
    shift[c] = beta2[c] - mu * sc;
}

// ---------------- final: BN2 apply + transpose ----------------
__global__ void final_kernel(const float* __restrict__ res, const float* __restrict__ xg,
                             const float* __restrict__ scale, const float* __restrict__ shift,
                             float* __restrict__ out)
{
    __shared__ float tile[32][33];
    const int b = blockIdx.z;
    const int n0 = blockIdx.x * 32;
    const int c0 = blockIdx.y * 32;
    const int tx = threadIdx.x, ty = threadIdx.y;
    #pragma unroll
    for (int k = 0; k < 4; k++) {
        const int n = n0 + ty + k * 8;
        const int c = c0 + tx;
        tile[ty + k * 8][tx] = res[((size_t)b * NNODE + n) * CCH + c] + xg[b * CCH + c];
    }
    __syncthreads();
    #pragma unroll
    for (int k = 0; k < 4; k++) {
        const int c = c0 + ty + k * 8;
        const int n = n0 + tx;
        out[((size_t)b * CCH + c) * NNODE + n] = tile[tx][ty + k * 8] * scale[c] + shift[c];
    }
}

// ---------------- launch ----------------
extern "C" void kernel_launch(void* const* d_in, const int* in_sizes, int n_in,
                              void* d_out, int out_size)
{
    const float* x = nullptr;
    const float* w[4] = {nullptr, nullptr, nullptr, nullptr};
    const float* v[7] = {nullptr, nullptr, nullptr, nullptr, nullptr, nullptr, nullptr};
    int wi = 0, vi = 0;
    for (int i = 0; i < n_in; i++) {
        const int sz = in_sizes[i];
        if (sz == MROWS * CCH) { if (!x) x = (const float*)d_in[i]; }
        else if (sz == CCH * CCH) { if (wi < 4) w[wi++] = (const float*)d_in[i]; }
        else if (sz == CCH) { if (vi < 7) v[vi++] = (const float*)d_in[i]; }
    }
    const float* b_pre = v[0]; const float* b_g1 = v[1]; const float* b_g2 = v[2];
    const float* g1 = v[3];    const float* beta1 = v[4];
    const float* g2 = v[5];    const float* beta2 = v[6];

    float *p_res, *p_t, *p_hp, *p_rs, *p_rq, *p_xg, *p_sc, *p_sh;
    __nv_bfloat16 *p_xh, *p_xl, *p_ah, *p_al, *p_wh, *p_wl;
    cudaGetSymbolAddress((void**)&p_res, g_res);
    cudaGetSymbolAddress((void**)&p_t, g_t);
    cudaGetSymbolAddress((void**)&p_xh, g_xh);
    cudaGetSymbolAddress((void**)&p_xl, g_xl);
    cudaGetSymbolAddress((void**)&p_ah, g_ah);
    cudaGetSymbolAddress((void**)&p_al, g_al);
    cudaGetSymbolAddress((void**)&p_wh, g_wh);
    cudaGetSymbolAddress((void**)&p_wl, g_wl);
    cudaGetSymbolAddress((void**)&p_hp, g_hp);
    cudaGetSymbolAddress((void**)&p_rs, g_rs);
    cudaGetSymbolAddress((void**)&p_rq, g_rq);
    cudaGetSymbolAddress((void**)&p_xg, g_xg);
    cudaGetSymbolAddress((void**)&p_sc, g_scale);
    cudaGetSymbolAddress((void**)&p_sh, g_shift);

    float* out = (float*)d_out;

    cudaFuncSetAttribute(gemm_mma, cudaFuncAttributeMaxDynamicSharedMemorySize, (int)GEMM_SMEM);

    const int agg_blocks = (BATCH * NNODE * (CCH / 4)) / 256;
    const dim3 wgrid(16, 16), wthr(32, 8);
    const size_t WB = (size_t)CCH * CCH;

    convert_x_kernel<<<(MROWS * CCH / 4) / 256, 256>>>(x, p_xh, p_xl);
    for (int i = 0; i < 4; i++)
        convert_w_kernel<<<wgrid, wthr>>>(w[i], p_wh + (size_t)i * WB, p_wl + (size_t)i * WB);

    // fused dual GEMM: ntile 0..3 -> residual (store + sum/sumsq partials),
    //                  ntile 4..7 -> xr = x@w_pre + b_pre (store)
    gemm_mma<<<dim3(8, 256), 256, GEMM_SMEM>>>(
        p_xh, p_xl, p_wh, p_wl,
        p_res, p_t, nullptr, b_pre, p_rs, p_rq,
        /*mode0=*/1 | 8 | 16, /*mode1=*/1 | 4);

    // a1 = Agg(xr)
    agg_split_kernel<<<agg_blocks, 256>>>(p_t, p_ah, p_al);
    // h1 = relu(a1 @ w_g1 + b_g1)
    gemm_mma<<<dim3(4, 256), 256, GEMM_SMEM>>>(
        p_ah, p_al, p_wh + 2 * WB, p_wl + 2 * WB,
        p_t, p_t, b_g1, nullptr, nullptr, nullptr,
        /*mode0=*/1 | 2 | 4, /*mode1=*/0);
    // a2 = Agg(h1)
    agg_split_kernel<<<agg_blocks, 256>>>(p_t, p_ah, p_al);
    // h2 = relu(a2 @ w_g2 + b_g2): no store, column-sum partials only
    gemm_mma<<<dim3(4, 256), 256, GEMM_SMEM>>>(
        p_ah, p_al, p_wh + 3 * WB, p_wl + 3 * WB,
        nullptr, nullptr, b_g2, nullptr, p_hp, nullptr,
        /*mode0=*/2 | 4 | 8, /*mode1=*/0);

    // tail
    bn1_kernel<<<1, CCH>>>(p_hp, g1, beta1, p_xg);
    stats_reduce_kernel<<<1, CCH>>>(p_rs, p_rq, p_xg, g2, beta2, p_sc, p_sh);
    final_kernel<<<dim3(NNODE / 32, CCH / 32, BATCH), dim3(32, 8)>>>(p_res, p_xg, p_sc, p_sh, out);
}

// round 5
// speedup vs baseline: 2.4405x; 1.0121x over previous
#include <cuda_runtime.h>
#include <cuda_bf16.h>
#include <cstdint>
#include <math.h>

#define BATCH 8
#define GH 64
#define GW 64
#define NNODE 4096
#define CCH 512
#define MROWS (BATCH * NNODE)
#define EPSV 1e-5f

// ---------------- scratch ----------------
__device__ float g_res[MROWS * CCH];
__device__ float g_t[MROWS * CCH];
__device__ __nv_bfloat16 g_ah[MROWS * CCH];
__device__ __nv_bfloat16 g_al[MROWS * CCH];
__device__ __nv_bfloat16 g_wh[4 * CCH * CCH];
__device__ __nv_bfloat16 g_wl[4 * CCH * CCH];
__device__ float g_hp[256 * CCH];
__device__ float g_rs[256 * CCH];
__device__ float g_rq[256 * CCH];
__device__ float g_xg[BATCH * CCH];
__device__ float g_scale[CCH];
__device__ float g_shift[CCH];

// ---------------- helpers ----------------
__device__ __forceinline__ uint32_t smem_u32(const void* p) {
    uint32_t a;
    asm("{ .reg .u64 t; cvta.to.shared.u64 t, %1; cvt.u32.u64 %0, t; }" : "=r"(a) : "l"(p));
    return a;
}
__device__ __forceinline__ void ldsm_x4(uint32_t addr, uint32_t* r) {
    asm volatile("ldmatrix.sync.aligned.m8n8.x4.shared.b16 {%0,%1,%2,%3}, [%4];"
                 : "=r"(r[0]), "=r"(r[1]), "=r"(r[2]), "=r"(r[3]) : "r"(addr));
}
__device__ __forceinline__ void mma16816(float* c, const uint32_t* a, const uint32_t* b) {
    asm volatile("mma.sync.aligned.m16n8k16.row.col.f32.bf16.bf16.f32 "
                 "{%0,%1,%2,%3}, {%4,%5,%6,%7}, {%8,%9}, {%0,%1,%2,%3};"
                 : "+f"(c[0]), "+f"(c[1]), "+f"(c[2]), "+f"(c[3])
                 : "r"(a[0]), "r"(a[1]), "r"(a[2]), "r"(a[3]), "r"(b[0]), "r"(b[1]));
}
__device__ __forceinline__ void cp16(uint32_t dst, const void* src) {
    asm volatile("cp.async.cg.shared.global [%0], [%1], 16;" :: "r"(dst), "l"(src) : "memory");
}
#define CP_COMMIT() asm volatile("cp.async.commit_group;" ::: "memory")
#define CP_WAIT0()  asm volatile("cp.async.wait_group 0;" ::: "memory")

// pack two floats -> bf16x2 (hi), residuals out
__device__ __forceinline__ uint32_t pk_hi(float x, float y, float& rx, float& ry) {
    __nv_bfloat16 hx = __float2bfloat16(x), hy = __float2bfloat16(y);
    rx = x - __bfloat162float(hx);
    ry = y - __bfloat162float(hy);
    return (uint32_t)__bfloat16_as_ushort(hx) | ((uint32_t)__bfloat16_as_ushort(hy) << 16);
}
__device__ __forceinline__ uint32_t pk(float x, float y) {
    return (uint32_t)__bfloat16_as_ushort(__float2bfloat16(x))
         | ((uint32_t)__bfloat16_as_ushort(__float2bfloat16(y)) << 16);
}

// ---------------- mma.sync split-bf16 GEMM ----------------
// mode bits: 1=store C, 2=relu, 4=bias, 8=column-sum partials, 16=also sumsq
// AFP32=1: A operand is fp32 (x); conversion to split-bf16 fused into A load path.
#define BKC 32
#define ROWB 80u
#define TILEB 10240u
#define STAGEB (4u * TILEB)
#define GEMM_SMEM (2u * STAGEB)

template<int AFP32>
__global__ __launch_bounds__(256, 2)
void gemm_mma(const void* __restrict__ A0, const void* __restrict__ A1,
              const __nv_bfloat16* __restrict__ Bh, const __nv_bfloat16* __restrict__ Bl,
              float* __restrict__ C0, float* __restrict__ C1,
              const float* __restrict__ bias0, const float* __restrict__ bias1,
              float* __restrict__ redS, float* __restrict__ redQ,
              int mode0, int mode1)
{
    extern __shared__ __align__(128) char smem[];
    const uint32_t sb = smem_u32(smem);
    const int tid = threadIdx.x;
    const int wid = tid >> 5;
    const int lane = tid & 31;
    const int wm = wid & 1;
    const int wn = wid >> 1;
    const int mtile = blockIdx.y;
    const int ntile = blockIdx.x;

    const __nv_bfloat16* src0 = (const __nv_bfloat16*)A0 + (size_t)mtile * 128 * 512;  // bf16 path
    const __nv_bfloat16* src1 = (const __nv_bfloat16*)A1 + (size_t)mtile * 128 * 512;
    const float* srcx = (const float*)A0 + (size_t)mtile * 128 * 512;                  // fp32 path
    const __nv_bfloat16* src2 = Bh + (size_t)ntile * 128 * 512;
    const __nv_bfloat16* src3 = Bl + (size_t)ntile * 128 * 512;

    float acc[4][4][4];
    #pragma unroll
    for (int i = 0; i < 4; i++)
        #pragma unroll
        for (int j = 0; j < 4; j++)
            #pragma unroll
            for (int k = 0; k < 4; k++) acc[i][j][k] = 0.f;

    const int lr = lane & 15;
    const int lk = lane >> 4;
    const int bn = (lane & 7) + ((lane >> 4) << 3);
    const int bk = ((lane >> 3) & 1) << 3;

    // fp32-A coordinates: 2 units/thread, unit = (row, ch of 8 k-values)
    const int au_row[2] = { tid >> 2, (256 + tid) >> 2 };
    const int au_ch = tid & 3;

    float4 ra[2][2];  // prefetch regs (fp32 path)

    // B cp.async for one stage (both paths)
    #define LOAD_B(kc, buf) do { \
        const int _kc = (kc); const uint32_t _sbase = sb + (buf) * STAGEB; \
        _Pragma("unroll") \
        for (int p = 0; p < 4; p++) { \
            const int id = 1024 + p * 256 + tid; \
            const int sel = id >> 9; \
            const int e = id & 511; \
            const int row = e >> 2, ch = e & 3; \
            const uint32_t dst = _sbase + (uint32_t)sel * TILEB + (uint32_t)row * ROWB + (uint32_t)ch * 16u; \
            const __nv_bfloat16* s = (sel == 2 ? src2 : src3) + (size_t)row * 512 + (size_t)_kc * BKC + ch * 8; \
            cp16(dst, s); \
        } \
    } while (0)

    // bf16-A cp.async for one stage
    #define LOAD_A_BF16(kc, buf) do { \
        const int _kc = (kc); const uint32_t _sbase = sb + (buf) * STAGEB; \
        _Pragma("unroll") \
        for (int p = 0; p < 4; p++) { \
            const int id = p * 256 + tid; \
            const int sel = id >> 9; \
            const int e = id & 511; \
            const int row = e >> 2, ch = e & 3; \
            const uint32_t dst = _sbase + (uint32_t)sel * TILEB + (uint32_t)row * ROWB + (uint32_t)ch * 16u; \
            const __nv_bfloat16* s = (sel == 0 ? src0 : src1) + (size_t)row * 512 + (size_t)_kc * BKC + ch * 8; \
            cp16(dst, s); \
        } \
    } while (0)

    // fp32-A register load for one k-chunk
    #define LOAD_A_F32(kc) do { \
        const int _kc = (kc); \
        _Pragma("unroll") \
        for (int i = 0; i < 2; i++) { \
            const float* s = srcx + (size_t)au_row[i] * 512 + (size_t)_kc * BKC + au_ch * 8; \
            ra[i][0] = *(const float4*)s; \
            ra[i][1] = *(const float4*)(s + 4); \
        } \
    } while (0)

    // fp32-A split + store to smem
    #define STORE_A_F32(buf) do { \
        const uint32_t _sbase = sb + (buf) * STAGEB; \
        _Pragma("unroll") \
        for (int i = 0; i < 2; i++) { \
            float r0, r1, r2, r3, r4, r5, r6, r7; \
            uint4 hi, lo; \
            hi.x = pk_hi(ra[i][0].x, ra[i][0].y, r0, r1); \
            hi.y = pk_hi(ra[i][0].z, ra[i][0].w, r2, r3); \
            hi.z = pk_hi(ra[i][1].x, ra[i][1].y, r4, r5); \
            hi.w = pk_hi(ra[i][1].z, ra[i][1].w, r6, r7); \
            lo.x = pk(r0, r1); lo.y = pk(r2, r3); lo.z = pk(r4, r5); lo.w = pk(r6, r7); \
            const uint32_t off = (uint32_t)au_row[i] * ROWB + (uint32_t)au_ch * 16u; \
            *(uint4*)(smem + ((buf) * STAGEB) + off) = hi; \
            *(uint4*)(smem + ((buf) * STAGEB) + TILEB + off) = lo; \
        } \
        (void)_sbase; \
    } while (0)

    // prologue: stage 0
    LOAD_B(0, 0);
    CP_COMMIT();
    if (AFP32) { LOAD_A_F32(0); STORE_A_F32(0); }
    else { LOAD_A_BF16(0, 0); CP_COMMIT(); }

    int buf = 0;
    #pragma unroll 1
    for (int kc = 0; kc < 16; kc++) {
        CP_WAIT0();
        __syncthreads();
        if (kc + 1 < 16) {
            LOAD_B(kc + 1, buf ^ 1);
            CP_COMMIT();
            if (AFP32) LOAD_A_F32(kc + 1);
            else { LOAD_A_BF16(kc + 1, buf ^ 1); CP_COMMIT(); }
        }

        const uint32_t base = sb + (uint32_t)buf * STAGEB;
        #pragma unroll
        for (int ks = 0; ks < 2; ks++) {
            uint32_t ah[4][4], al[4][4];
            #pragma unroll
            for (int mi = 0; mi < 4; mi++) {
                const uint32_t off = (uint32_t)(wm * 64 + mi * 16 + lr) * ROWB
                                   + (uint32_t)(ks * 16 + lk * 8) * 2u;
                ldsm_x4(base + off, ah[mi]);
                ldsm_x4(base + TILEB + off, al[mi]);
            }
            #pragma unroll
            for (int np = 0; np < 2; np++) {
                uint32_t bh[2][2], bl[2][2];
                const uint32_t off = (uint32_t)(wn * 32 + np * 16 + bn) * ROWB
                                   + (uint32_t)(ks * 16 + bk) * 2u;
                uint32_t r[4];
                ldsm_x4(base + 2u * TILEB + off, r);
                bh[0][0] = r[0]; bh[0][1] = r[1]; bh[1][0] = r[2]; bh[1][1] = r[3];
                ldsm_x4(base + 3u * TILEB + off, r);
                bl[0][0] = r[0]; bl[0][1] = r[1]; bl[1][0] = r[2]; bl[1][1] = r[3];
                #pragma unroll
                for (int mi = 0; mi < 4; mi++)
                    #pragma unroll
                    for (int b2 = 0; b2 < 2; b2++) {
                        const int nb = np * 2 + b2;
                        mma16816(acc[mi][nb], ah[mi], bh[b2]);
                        mma16816(acc[mi][nb], ah[mi], bl[b2]);
                        mma16816(acc[mi][nb], al[mi], bh[b2]);
                    }
            }
        }
        if (AFP32 && (kc + 1 < 16)) STORE_A_F32(buf ^ 1);
        buf ^= 1;
    }

    // ---------------- epilogue ----------------
    const int selc = ntile >> 2;
    const int mode = selc ? mode1 : mode0;
    const float* bias = selc ? bias1 : bias0;
    float* C = selc ? C1 : C0;
    const int ncol = (ntile & 3) * 128;

    const int gid = lane >> 2;
    const int tig = lane & 3;

    float rsum[4][2], rq[4][2];
    #pragma unroll
    for (int nb = 0; nb < 4; nb++) { rsum[nb][0] = rsum[nb][1] = rq[nb][0] = rq[nb][1] = 0.f; }

    #pragma unroll
    for (int mi = 0; mi < 4; mi++) {
        const int row0 = mtile * 128 + wm * 64 + mi * 16 + gid;
        #pragma unroll
        for (int nb = 0; nb < 4; nb++) {
            const int col = ncol + wn * 32 + nb * 8 + tig * 2;
            float b0 = 0.f, b1 = 0.f;
            if (mode & 4) { b0 = __ldg(bias + col); b1 = __ldg(bias + col + 1); }
            float v0 = acc[mi][nb][0] + b0, v1 = acc[mi][nb][1] + b1;
            float v2 = acc[mi][nb][2] + b0, v3 = acc[mi][nb][3] + b1;
            if (mode & 2) {
                v0 = fmaxf(v0, 0.f); v1 = fmaxf(v1, 0.f);
                v2 = fmaxf(v2, 0.f); v3 = fmaxf(v3, 0.f);
            }
            if (mode & 1) {
                *(float2*)(C + (size_t)row0 * 512 + col) = make_float2(v0, v1);
                *(float2*)(C + (size_t)(row0 + 8) * 512 + col) = make_float2(v2, v3);
            }
            if (mode & 8) {
                rsum[nb][0] += v0 + v2; rsum[nb][1] += v1 + v3;
                if (mode & 16) {
                    rq[nb][0] = fmaf(v0, v0, fmaf(v2, v2, rq[nb][0]));
                    rq[nb][1] = fmaf(v1, v1, fmaf(v3, v3, rq[nb][1]));
                }
            }
        }
    }

    if (mode & 8) {
        #pragma unroll
        for (int nb = 0; nb < 4; nb++)
            #pragma unroll
            for (int j = 0; j < 2; j++) {
                #pragma unroll
                for (int m = 4; m <= 16; m <<= 1) {
                    rsum[nb][j] += __shfl_xor_sync(0xffffffffu, rsum[nb][j], m);
                    rq[nb][j]   += __shfl_xor_sync(0xffffffffu, rq[nb][j], m);
                }
            }
        __syncthreads();
        float* red = (float*)smem;
        if (gid == 0) {
            #pragma unroll
            for (int nb = 0; nb < 4; nb++) {
                const int c = wn * 32 + nb * 8 + tig * 2;
                red[wm * 128 + c]     = rsum[nb][0];
                red[wm * 128 + c + 1] = rsum[nb][1];
                red[256 + wm * 128 + c]     = rq[nb][0];
                red[256 + wm * 128 + c + 1] = rq[nb][1];
            }
        }
        __syncthreads();
        if (tid < 128) {
            const float s = red[tid] + red[128 + tid];
            redS[(size_t)mtile * 512 + ncol + tid] = s;
            if (mode & 16) {
                const float q = red[256 + tid] + red[384 + tid];
                redQ[(size_t)mtile * 512 + ncol + tid] = q;
            }
        }
    }
}

// ---------------- convert+transpose weights (all 4 in one launch) ----------------
__global__ void convert_w_kernel(const float* __restrict__ w0, const float* __restrict__ w1,
                                 const float* __restrict__ w2, const float* __restrict__ w3,
                                 __nv_bfloat16* __restrict__ wh, __nv_bfloat16* __restrict__ wl)
{
    __shared__ float t[32][33];
    const int wsel = blockIdx.z;
    const float* w = wsel == 0 ? w0 : wsel == 1 ? w1 : wsel == 2 ? w2 : w3;
    __nv_bfloat16* oh = wh + (size_t)wsel * CCH * CCH;
    __nv_bfloat16* ol = wl + (size_t)wsel * CCH * CCH;
    const int n0 = blockIdx.x * 32;
    const int k0 = blockIdx.y * 32;
    const int tx = threadIdx.x, ty = threadIdx.y;
    #pragma unroll
    for (int j = 0; j < 4; j++)
        t[ty + j * 8][tx] = w[(size_t)(k0 + ty + j * 8) * 512 + n0 + tx];
    __syncthreads();
    #pragma unroll
    for (int j = 0; j < 4; j++) {
        const float v = t[tx][ty + j * 8];
        const __nv_bfloat16 hb = __float2bfloat16(v);
        oh[(size_t)(n0 + ty + j * 8) * 512 + k0 + tx] = hb;
        ol[(size_t)(n0 + ty + j * 8) * 512 + k0 + tx] = __float2bfloat16(v - __bfloat162float(hb));
    }
}

// ---------------- GCN aggregation (fp32 in -> bf16 hi/lo out) ----------------
__device__ __forceinline__ float degf(int r, int c) {
    return 1.f + (float)(c > 0) + (float)(c < GW - 1) + (float)(r > 0) + (float)(r < GH - 1);
}

__global__ void agg_split_kernel(const float* __restrict__ in,
                                 __nv_bfloat16* __restrict__ oh, __nv_bfloat16* __restrict__ ol)
{
    const int idx = blockIdx.x * 256 + threadIdx.x;
    const int c4 = idx & 127;
    const int node = (idx >> 7) & (NNODE - 1);
    const int b = idx >> 19;
    const int r = node >> 6;
    const int cc = node & 63;

    const float4* base = (const float4*)in + (size_t)b * NNODE * 128 + c4;
    const float dg = degf(r, cc);
    const float di = rsqrtf(dg);

    float4 v = base[(size_t)node * 128];
    float ax = di * v.x, ay = di * v.y, az = di * v.z, aw = di * v.w;
    if (cc > 0) {
        const float dj = rsqrtf(degf(r, cc - 1));
        float4 w = base[(size_t)(node - 1) * 128];
        ax = fmaf(dj, w.x, ax); ay = fmaf(dj, w.y, ay); az = fmaf(dj, w.z, az); aw = fmaf(dj, w.w, aw);
    }
    if (cc < GW - 1) {
        const float dj = rsqrtf(degf(r, cc + 1));
        float4 w = base[(size_t)(node + 1) * 128];
        ax = fmaf(dj, w.x, ax); ay = fmaf(dj, w.y, ay); az = fmaf(dj, w.z, az); aw = fmaf(dj, w.w, aw);
    }
    if (r > 0) {
        const float dj = rsqrtf(degf(r - 1, cc));
        float4 w = base[(size_t)(node - GW) * 128];
        ax = fmaf(dj, w.x, ax); ay = fmaf(dj, w.y, ay); az = fmaf(dj, w.z, az); aw = fmaf(dj, w.w, aw);
    }
    if (r < GH - 1) {
        const float dj = rsqrtf(degf(r + 1, cc));
        float4 w = base[(size_t)(node + GW) * 128];
        ax = fmaf(dj, w.x, ax); ay = fmaf(dj, w.y, ay); az = fmaf(dj, w.z, az); aw = fmaf(dj, w.w, aw);
    }
    const float sc = di / dg;
    float r0, r1, r2, r3;
    uint2 hi, lo;
    hi.x = pk_hi(sc * ax, sc * ay, r0, r1);
    hi.y = pk_hi(sc * az, sc * aw, r2, r3);
    lo.x = pk(r0, r1);
    lo.y = pk(r2, r3);
    const size_t e = ((size_t)b * NNODE * CCH + (size_t)node * CCH) / 4 + c4;
    ((uint2*)oh)[e] = hi;
    ((uint2*)ol)[e] = lo;
}

// ---------------- BN1 from fused h2 partials ----------------
__global__ void bn1_kernel(const float* __restrict__ hp,
                           const float* __restrict__ g1, const float* __restrict__ beta1,
                           float* __restrict__ xg)
{
    const int c = threadIdx.x;
    float pooled[BATCH];
    float mu = 0.f;
    #pragma unroll
    for (int b = 0; b < BATCH; b++) {
        float s = 0.f;
        #pragma unroll 8
        for (int k = 0; k < 32; k++) s += hp[(size_t)(b * 32 + k) * CCH + c];
        pooled[b] = s * (1.f / (float)NNODE);
        mu += pooled[b];
    }
    mu *= (1.f / (float)BATCH);
    float var = 0.f;
    #pragma unroll
    for (int b = 0; b < BATCH; b++) { const float d = pooled[b] - mu; var = fmaf(d, d, var); }
    var *= (1.f / (float)BATCH);
    const float inv = rsqrtf(var + EPSV);
    const float ga = g1[c], be = beta1[c];
    #pragma unroll
    for (int b = 0; b < BATCH; b++)
        xg[b * CCH + c] = (pooled[b] - mu) * inv * ga + be;
}

// ---------------- BN2 scale/shift ----------------
__global__ void stats_reduce_kernel(const float* __restrict__ rs, const float* __restrict__ rq,
                                    const float* __restrict__ xg,
                                    const float* __restrict__ g2, const float* __restrict__ beta2,
                                    float* __restrict__ scale, float* __restrict__ shift)
{
    const int c = threadIdx.x;
    float S = 0.f, Q = 0.f;
    #pragma unroll
    for (int b = 0; b < BATCH; b++) {
        float sb = 0.f, qb = 0.f;
        #pragma unroll 8
        for (int k = 0; k < 32; k++) {
            const size_t idx = (size_t)(b * 32 + k) * CCH + c;
            sb += rs[idx]; qb += rq[idx];
        }
        const float xv = xg[b * CCH + c];
        S += sb + 4096.f * xv;
        Q += qb + 2.f * xv * sb + 4096.f * xv * xv;
    }
    const float mu = S * (1.f / (float)MROWS);
    float var = Q * (1.f / (float)MROWS) - mu * mu;
    var = fmaxf(var, 0.f);
    const float inv = rsqrtf(var + EPSV);
    const float sc = inv * g2[c];
    scale[c] = sc;
    shift[c] = beta2[c] - mu * sc;
}

// ---------------- final: BN2 apply + transpose ----------------
__global__ void final_kernel(const float* __restrict__ res, const float* __restrict__ xg,
                             const float* __restrict__ scale, const float* __restrict__ shift,
                             float* __restrict__ out)
{
    __shared__ float tile[32][33];
    const int b = blockIdx.z;
    const int n0 = blockIdx.x * 32;
    const int c0 = blockIdx.y * 32;
    const int tx = threadIdx.x, ty = threadIdx.y;
    #pragma unroll
    for (int k = 0; k < 4; k++) {
        const int n = n0 + ty + k * 8;
        const int c = c0 + tx;
        tile[ty + k * 8][tx] = res[((size_t)b * NNODE + n) * CCH + c] + xg[b * CCH + c];
    }
    __syncthreads();
    #pragma unroll
    for (int k = 0; k < 4; k++) {
        const int c = c0 + ty + k * 8;
        const int n = n0 + tx;
        out[((size_t)b * CCH + c) * NNODE + n] = tile[tx][ty + k * 8] * scale[c] + shift[c];
    }
}

// ---------------- launch ----------------
extern "C" void kernel_launch(void* const* d_in, const int* in_sizes, int n_in,
                              void* d_out, int out_size)
{
    const float* x = nullptr;
    const float* w[4] = {nullptr, nullptr, nullptr, nullptr};
    const float* v[7] = {nullptr, nullptr, nullptr, nullptr, nullptr, nullptr, nullptr};
    int wi = 0, vi = 0;
    for (int i = 0; i < n_in; i++) {
        const int sz = in_sizes[i];
        if (sz == MROWS * CCH) { if (!x) x = (const float*)d_in[i]; }
        else if (sz == CCH * CCH) { if (wi < 4) w[wi++] = (const float*)d_in[i]; }
        else if (sz == CCH) { if (vi < 7) v[vi++] = (const float*)d_in[i]; }
    }
    const float* b_pre = v[0]; const float* b_g1 = v[1]; const float* b_g2 = v[2];
    const float* g1 = v[3];    const float* beta1 = v[4];
    const float* g2 = v[5];    const float* beta2 = v[6];

    float *p_res, *p_t, *p_hp, *p_rs, *p_rq, *p_xg, *p_sc, *p_sh;
    __nv_bfloat16 *p_ah, *p_al, *p_wh, *p_wl;
    cudaGetSymbolAddress((void**)&p_res, g_res);
    cudaGetSymbolAddress((void**)&p_t, g_t);
    cudaGetSymbolAddress((void**)&p_ah, g_ah);
    cudaGetSymbolAddress((void**)&p_al, g_al);
    cudaGetSymbolAddress((void**)&p_wh, g_wh);
    cudaGetSymbolAddress((void**)&p_wl, g_wl);
    cudaGetSymbolAddress((void**)&p_hp, g_hp);
    cudaGetSymbolAddress((void**)&p_rs, g_rs);
    cudaGetSymbolAddress((void**)&p_rq, g_rq);
    cudaGetSymbolAddress((void**)&p_xg, g_xg);
    cudaGetSymbolAddress((void**)&p_sc, g_scale);
    cudaGetSymbolAddress((void**)&p_sh, g_shift);

    float* out = (float*)d_out;

    cudaFuncSetAttribute(gemm_mma<0>, cudaFuncAttributeMaxDynamicSharedMemorySize, (int)GEMM_SMEM);
    cudaFuncSetAttribute(gemm_mma<1>, cudaFuncAttributeMaxDynamicSharedMemorySize, (int)GEMM_SMEM);

    const int agg_blocks = (BATCH * NNODE * (CCH / 4)) / 256;
    const size_t WB = (size_t)CCH * CCH;

    // weights: all 4 converted+transposed in one launch
    convert_w_kernel<<<dim3(16, 16, 4), dim3(32, 8)>>>(w[0], w[1], w[2], w[3], p_wh, p_wl);

    // fused dual GEMM on fp32 x: ntile 0..3 -> residual (store + stats partials),
    //                            ntile 4..7 -> xr = x@w_pre + b_pre (store)
    gemm_mma<1><<<dim3(8, 256), 256, GEMM_SMEM>>>(
        x, nullptr, p_wh, p_wl,
        p_res, p_t, nullptr, b_pre, p_rs, p_rq,
        /*mode0=*/1 | 8 | 16, /*mode1=*/1 | 4);

    // a1 = Agg(xr)
    agg_split_kernel<<<agg_blocks, 256>>>(p_t, p_ah, p_al);
    // h1 = relu(a1 @ w_g1 + b_g1)
    gemm_mma<0><<<dim3(4, 256), 256, GEMM_SMEM>>>(
        p_ah, p_al, p_wh + 2 * WB, p_wl + 2 * WB,
        p_t, p_t, b_g1, nullptr, nullptr, nullptr,
        /*mode0=*/1 | 2 | 4, /*mode1=*/0);
    // a2 = Agg(h1)
    agg_split_kernel<<<agg_blocks, 256>>>(p_t, p_ah, p_al);
    // h2 = relu(a2 @ w_g2 + b_g2): no store, column-sum partials only
    gemm_mma<0><<<dim3(4, 256), 256, GEMM_SMEM>>>(
        p_ah, p_al, p_wh + 3 * WB, p_wl + 3 * WB,
        nullptr, nullptr, b_g2, nullptr, p_hp, nullptr,
        /*mode0=*/2 | 4 | 8, /*mode1=*/0);

    // tail
    bn1_kernel<<<1, CCH>>>(p_hp, g1, beta1, p_xg);
    stats_reduce_kernel<<<1, CCH>>>(p_rs, p_rq, p_xg, g2, beta2, p_sc, p_sh);
    final_kernel<<<dim3(NNODE / 32, CCH / 32, BATCH), dim3(32, 8)>>>(p_res, p_xg, p_sc, p_sh, out);
}

// round 6
// speedup vs baseline: 2.4547x; 1.0058x over previous
#include <cuda_runtime.h>
#include <cuda_bf16.h>
#include <cstdint>
#include <math.h>

#define BATCH 8
#define GH 64
#define GW 64
#define NNODE 4096
#define CCH 512
#define MROWS (BATCH * NNODE)
#define EPSV 1e-5f

// ---------------- scratch ----------------
__device__ float g_res[MROWS * CCH];
__device__ float g_t[MROWS * CCH];
__device__ __nv_bfloat16 g_ah[MROWS * CCH];
__device__ __nv_bfloat16 g_al[MROWS * CCH];
__device__ __nv_bfloat16 g_wh[4 * CCH * CCH];
__device__ __nv_bfloat16 g_wl[4 * CCH * CCH];
__device__ float g_hp[256 * CCH];
__device__ float g_rs[256 * CCH];
__device__ float g_rq[256 * CCH];
__device__ float g_xg[BATCH * CCH];
__device__ float g_scale[CCH];
__device__ float g_shift[CCH];

// ---------------- helpers ----------------
__device__ __forceinline__ uint32_t smem_u32(const void* p) {
    uint32_t a;
    asm("{ .reg .u64 t; cvta.to.shared.u64 t, %1; cvt.u32.u64 %0, t; }" : "=r"(a) : "l"(p));
    return a;
}
__device__ __forceinline__ void ldsm_x4(uint32_t addr, uint32_t* r) {
    asm volatile("ldmatrix.sync.aligned.m8n8.x4.shared.b16 {%0,%1,%2,%3}, [%4];"
                 : "=r"(r[0]), "=r"(r[1]), "=r"(r[2]), "=r"(r[3]) : "r"(addr));
}
__device__ __forceinline__ void mma16816(float* c, const uint32_t* a, const uint32_t* b) {
    asm volatile("mma.sync.aligned.m16n8k16.row.col.f32.bf16.bf16.f32 "
                 "{%0,%1,%2,%3}, {%4,%5,%6,%7}, {%8,%9}, {%0,%1,%2,%3};"
                 : "+f"(c[0]), "+f"(c[1]), "+f"(c[2]), "+f"(c[3])
                 : "r"(a[0]), "r"(a[1]), "r"(a[2]), "r"(a[3]), "r"(b[0]), "r"(b[1]));
}
__device__ __forceinline__ void cp16(uint32_t dst, const void* src) {
    asm volatile("cp.async.cg.shared.global [%0], [%1], 16;" :: "r"(dst), "l"(src) : "memory");
}
#define CP_COMMIT() asm volatile("cp.async.commit_group;" ::: "memory")
#define CP_WAIT0()  asm volatile("cp.async.wait_group 0;" ::: "memory")

__device__ __forceinline__ uint32_t pk_hi(float x, float y, float& rx, float& ry) {
    __nv_bfloat16 hx = __float2bfloat16(x), hy = __float2bfloat16(y);
    rx = x - __bfloat162float(hx);
    ry = y - __bfloat162float(hy);
    return (uint32_t)__bfloat16_as_ushort(hx) | ((uint32_t)__bfloat16_as_ushort(hy) << 16);
}
__device__ __forceinline__ uint32_t pk(float x, float y) {
    return (uint32_t)__bfloat16_as_ushort(__float2bfloat16(x))
         | ((uint32_t)__bfloat16_as_ushort(__float2bfloat16(y)) << 16);
}

// ---------------- mma.sync split-bf16 GEMM ----------------
// mode bits: 1=store C, 2=relu, 4=bias, 8=column-sum partials, 16=also sumsq
#define BKC 32
#define ROWB 80u
#define TILEB 10240u
#define STAGEB (4u * TILEB)
#define GEMM_SMEM (2u * STAGEB)

template<int AFP32>
__global__ __launch_bounds__(256, 2)
void gemm_mma(const void* __restrict__ A0, const void* __restrict__ A1,
              const __nv_bfloat16* __restrict__ Bh, const __nv_bfloat16* __restrict__ Bl,
              float* __restrict__ C0, float* __restrict__ C1,
              const float* __restrict__ bias0, const float* __restrict__ bias1,
              float* __restrict__ redS, float* __restrict__ redQ,
              int mode0, int mode1)
{
    extern __shared__ __align__(128) char smem[];
    const uint32_t sb = smem_u32(smem);
    const int tid = threadIdx.x;
    const int wid = tid >> 5;
    const int lane = tid & 31;
    const int wm = wid & 1;
    const int wn = wid >> 1;
    const int mtile = blockIdx.y;
    const int ntile = blockIdx.x;

    const __nv_bfloat16* src0 = (const __nv_bfloat16*)A0 + (size_t)mtile * 128 * 512;
    const __nv_bfloat16* src1 = (const __nv_bfloat16*)A1 + (size_t)mtile * 128 * 512;
    const float* srcx = (const float*)A0 + (size_t)mtile * 128 * 512;
    const __nv_bfloat16* src2 = Bh + (size_t)ntile * 128 * 512;
    const __nv_bfloat16* src3 = Bl + (size_t)ntile * 128 * 512;

    float acc[4][4][4];
    #pragma unroll
    for (int i = 0; i < 4; i++)
        #pragma unroll
        for (int j = 0; j < 4; j++)
            #pragma unroll
            for (int k = 0; k < 4; k++) acc[i][j][k] = 0.f;

    const int lr = lane & 15;
    const int lk = lane >> 4;
    const int bn = (lane & 7) + ((lane >> 4) << 3);
    const int bk = ((lane >> 3) & 1) << 3;

    const int au_row[2] = { tid >> 2, (256 + tid) >> 2 };
    const int au_ch = tid & 3;
    float4 ra[2][2];

    #define LOAD_B(kc, buf) do { \
        const int _kc = (kc); const uint32_t _sbase = sb + (buf) * STAGEB; \
        _Pragma("unroll") \
        for (int p = 0; p < 4; p++) { \
            const int id = 1024 + p * 256 + tid; \
            const int sel = id >> 9; \
            const int e = id & 511; \
            const int row = e >> 2, ch = e & 3; \
            const uint32_t dst = _sbase + (uint32_t)sel * TILEB + (uint32_t)row * ROWB + (uint32_t)ch * 16u; \
            const __nv_bfloat16* s = (sel == 2 ? src2 : src3) + (size_t)row * 512 + (size_t)_kc * BKC + ch * 8; \
            cp16(dst, s); \
        } \
    } while (0)

    #define LOAD_A_BF16(kc, buf) do { \
        const int _kc = (kc); const uint32_t _sbase = sb + (buf) * STAGEB; \
        _Pragma("unroll") \
        for (int p = 0; p < 4; p++) { \
            const int id = p * 256 + tid; \
            const int sel = id >> 9; \
            const int e = id & 511; \
            const int row = e >> 2, ch = e & 3; \
            const uint32_t dst = _sbase + (uint32_t)sel * TILEB + (uint32_t)row * ROWB + (uint32_t)ch * 16u; \
            const __nv_bfloat16* s = (sel == 0 ? src0 : src1) + (size_t)row * 512 + (size_t)_kc * BKC + ch * 8; \
            cp16(dst, s); \
        } \
    } while (0)

    #define LOAD_A_F32(kc) do { \
        const int _kc = (kc); \
        _Pragma("unroll") \
        for (int i = 0; i < 2; i++) { \
            const float* s = srcx + (size_t)au_row[i] * 512 + (size_t)_kc * BKC + au_ch * 8; \
            ra[i][0] = *(const float4*)s; \
            ra[i][1] = *(const float4*)(s + 4); \
        } \
    } while (0)

    #define STORE_A_F32(buf) do { \
        _Pragma("unroll") \
        for (int i = 0; i < 2; i++) { \
            float r0, r1, r2, r3, r4, r5, r6, r7; \
            uint4 hi, lo; \
            hi.x = pk_hi(ra[i][0].x, ra[i][0].y, r0, r1); \
            hi.y = pk_hi(ra[i][0].z, ra[i][0].w, r2, r3); \
            hi.z = pk_hi(ra[i][1].x, ra[i][1].y, r4, r5); \
            hi.w = pk_hi(ra[i][1].z, ra[i][1].w, r6, r7); \
            lo.x = pk(r0, r1); lo.y = pk(r2, r3); lo.z = pk(r4, r5); lo.w = pk(r6, r7); \
            const uint32_t off = (uint32_t)au_row[i] * ROWB + (uint32_t)au_ch * 16u; \
            *(uint4*)(smem + ((buf) * STAGEB) + off) = hi; \
            *(uint4*)(smem + ((buf) * STAGEB) + TILEB + off) = lo; \
        } \
    } while (0)

    LOAD_B(0, 0);
    CP_COMMIT();
    if (AFP32) { LOAD_A_F32(0); STORE_A_F32(0); }
    else { LOAD_A_BF16(0, 0); CP_COMMIT(); }

    int buf = 0;
    #pragma unroll 1
    for (int kc = 0; kc < 16; kc++) {
        CP_WAIT0();
        __syncthreads();
        if (kc + 1 < 16) {
            LOAD_B(kc + 1, buf ^ 1);
            CP_COMMIT();
            if (AFP32) LOAD_A_F32(kc + 1);
            else { LOAD_A_BF16(kc + 1, buf ^ 1); CP_COMMIT(); }
        }

        const uint32_t base = sb + (uint32_t)buf * STAGEB;
        #pragma unroll
        for (int ks = 0; ks < 2; ks++) {
            uint32_t ah[4][4], al[4][4];
            #pragma unroll
            for (int mi = 0; mi < 4; mi++) {
                const uint32_t off = (uint32_t)(wm * 64 + mi * 16 + lr) * ROWB
                                   + (uint32_t)(ks * 16 + lk * 8) * 2u;
                ldsm_x4(base + off, ah[mi]);
                ldsm_x4(base + TILEB + off, al[mi]);
            }
            #pragma unroll
            for (int np = 0; np < 2; np++) {
                uint32_t bh[2][2], bl[2][2];
                const uint32_t off = (uint32_t)(wn * 32 + np * 16 + bn) * ROWB
                                   + (uint32_t)(ks * 16 + bk) * 2u;
                uint32_t r[4];
                ldsm_x4(base + 2u * TILEB + off, r);
                bh[0][0] = r[0]; bh[0][1] = r[1]; bh[1][0] = r[2]; bh[1][1] = r[3];
                ldsm_x4(base + 3u * TILEB + off, r);
                bl[0][0] = r[0]; bl[0][1] = r[1]; bl[1][0] = r[2]; bl[1][1] = r[3];
                // term-major ordering: 8 independent accumulators between
                // successive writes to the same acc -> no RAW pipe bubbles
                #pragma unroll
                for (int mi = 0; mi < 4; mi++)
                    #pragma unroll
                    for (int b2 = 0; b2 < 2; b2++)
                        mma16816(acc[mi][np * 2 + b2], ah[mi], bh[b2]);
                #pragma unroll
                for (int mi = 0; mi < 4; mi++)
                    #pragma unroll
                    for (int b2 = 0; b2 < 2; b2++)
                        mma16816(acc[mi][np * 2 + b2], ah[mi], bl[b2]);
                #pragma unroll
                for (int mi = 0; mi < 4; mi++)
                    #pragma unroll
                    for (int b2 = 0; b2 < 2; b2++)
                        mma16816(acc[mi][np * 2 + b2], al[mi], bh[b2]);
            }
        }
        if (AFP32 && (kc + 1 < 16)) STORE_A_F32(buf ^ 1);
        buf ^= 1;
    }

    // ---------------- epilogue ----------------
    const int selc = ntile >> 2;
    const int mode = selc ? mode1 : mode0;
    const float* bias = selc ? bias1 : bias0;
    float* C = selc ? C1 : C0;
    const int ncol = (ntile & 3) * 128;

    const int gid = lane >> 2;
    const int tig = lane & 3;

    float rsum[4][2], rq[4][2];
    #pragma unroll
    for (int nb = 0; nb < 4; nb++) { rsum[nb][0] = rsum[nb][1] = rq[nb][0] = rq[nb][1] = 0.f; }

    #pragma unroll
    for (int mi = 0; mi < 4; mi++) {
        const int row0 = mtile * 128 + wm * 64 + mi * 16 + gid;
        #pragma unroll
        for (int nb = 0; nb < 4; nb++) {
            const int col = ncol + wn * 32 + nb * 8 + tig * 2;
            float b0 = 0.f, b1 = 0.f;
            if (mode & 4) { b0 = __ldg(bias + col); b1 = __ldg(bias + col + 1); }
            float v0 = acc[mi][nb][0] + b0, v1 = acc[mi][nb][1] + b1;
            float v2 = acc[mi][nb][2] + b0, v3 = acc[mi][nb][3] + b1;
            if (mode & 2) {
                v0 = fmaxf(v0, 0.f); v1 = fmaxf(v1, 0.f);
                v2 = fmaxf(v2, 0.f); v3 = fmaxf(v3, 0.f);
            }
            if (mode & 1) {
                *(float2*)(C + (size_t)row0 * 512 + col) = make_float2(v0, v1);
                *(float2*)(C + (size_t)(row0 + 8) * 512 + col) = make_float2(v2, v3);
            }
            if (mode & 8) {
                rsum[nb][0] += v0 + v2; rsum[nb][1] += v1 + v3;
                if (mode & 16) {
                    rq[nb][0] = fmaf(v0, v0, fmaf(v2, v2, rq[nb][0]));
                    rq[nb][1] = fmaf(v1, v1, fmaf(v3, v3, rq[nb][1]));
                }
            }
        }
    }

    if (mode & 8) {
        #pragma unroll
        for (int nb = 0; nb < 4; nb++)
            #pragma unroll
            for (int j = 0; j < 2; j++) {
                #pragma unroll
                for (int m = 4; m <= 16; m <<= 1) {
                    rsum[nb][j] += __shfl_xor_sync(0xffffffffu, rsum[nb][j], m);
                    rq[nb][j]   += __shfl_xor_sync(0xffffffffu, rq[nb][j], m);
                }
            }
        __syncthreads();
        float* red = (float*)smem;
        if (gid == 0) {
            #pragma unroll
            for (int nb = 0; nb < 4; nb++) {
                const int c = wn * 32 + nb * 8 + tig * 2;
                red[wm * 128 + c]     = rsum[nb][0];
                red[wm * 128 + c + 1] = rsum[nb][1];
                red[256 + wm * 128 + c]     = rq[nb][0];
                red[256 + wm * 128 + c + 1] = rq[nb][1];
            }
        }
        __syncthreads();
        if (tid < 128) {
            const float s = red[tid] + red[128 + tid];
            redS[(size_t)mtile * 512 + ncol + tid] = s;
            if (mode & 16) {
                const float q = red[256 + tid] + red[384 + tid];
                redQ[(size_t)mtile * 512 + ncol + tid] = q;
            }
        }
    }
}

// ---------------- convert+transpose weights (all 4, one launch) ----------------
__global__ void convert_w_kernel(const float* __restrict__ w0, const float* __restrict__ w1,
                                 const float* __restrict__ w2, const float* __restrict__ w3,
                                 __nv_bfloat16* __restrict__ wh, __nv_bfloat16* __restrict__ wl)
{
    __shared__ float t[32][33];
    const int wsel = blockIdx.z;
    const float* w = wsel == 0 ? w0 : wsel == 1 ? w1 : wsel == 2 ? w2 : w3;
    __nv_bfloat16* oh = wh + (size_t)wsel * CCH * CCH;
    __nv_bfloat16* ol = wl + (size_t)wsel * CCH * CCH;
    const int n0 = blockIdx.x * 32;
    const int k0 = blockIdx.y * 32;
    const int tx = threadIdx.x, ty = threadIdx.y;
    #pragma unroll
    for (int j = 0; j < 4; j++)
        t[ty + j * 8][tx] = w[(size_t)(k0 + ty + j * 8) * 512 + n0 + tx];
    __syncthreads();
    #pragma unroll
    for (int j = 0; j < 4; j++) {
        const float v = t[tx][ty + j * 8];
        const __nv_bfloat16 hb = __float2bfloat16(v);
        oh[(size_t)(n0 + ty + j * 8) * 512 + k0 + tx] = hb;
        ol[(size_t)(n0 + ty + j * 8) * 512 + k0 + tx] = __float2bfloat16(v - __bfloat162float(hb));
    }
}

// ---------------- GCN aggregation ----------------
__device__ __forceinline__ float degf(int r, int c) {
    return 1.f + (float)(c > 0) + (float)(c < GW - 1) + (float)(r > 0) + (float)(r < GH - 1);
}

__global__ void agg_split_kernel(const float* __restrict__ in,
                                 __nv_bfloat16* __restrict__ oh, __nv_bfloat16* __restrict__ ol)
{
    const int idx = blockIdx.x * 256 + threadIdx.x;
    const int c4 = idx & 127;
    const int node = (idx >> 7) & (NNODE - 1);
    const int b = idx >> 19;
    const int r = node >> 6;
    const int cc = node & 63;

    const float4* base = (const float4*)in + (size_t)b * NNODE * 128 + c4;
    const float dg = degf(r, cc);
    const float di = rsqrtf(dg);

    float4 v = base[(size_t)node * 128];
    float ax = di * v.x, ay = di * v.y, az = di * v.z, aw = di * v.w;
    if (cc > 0) {
        const float dj = rsqrtf(degf(r, cc - 1));
        float4 w = base[(size_t)(node - 1) * 128];
        ax = fmaf(dj, w.x, ax); ay = fmaf(dj, w.y, ay); az = fmaf(dj, w.z, az); aw = fmaf(dj, w.w, aw);
    }
    if (cc < GW - 1) {
        const float dj = rsqrtf(degf(r, cc + 1));
        float4 w = base[(size_t)(node + 1) * 128];
        ax = fmaf(dj, w.x, ax); ay = fmaf(dj, w.y, ay); az = fmaf(dj, w.z, az); aw = fmaf(dj, w.w, aw);
    }
    if (r > 0) {
        const float dj = rsqrtf(degf(r - 1, cc));
        float4 w = base[(size_t)(node - GW) * 128];
        ax = fmaf(dj, w.x, ax); ay = fmaf(dj, w.y, ay); az = fmaf(dj, w.z, az); aw = fmaf(dj, w.w, aw);
    }
    if (r < GH - 1) {
        const float dj = rsqrtf(degf(r + 1, cc));
        float4 w = base[(size_t)(node + GW) * 128];
        ax = fmaf(dj, w.x, ax); ay = fmaf(dj, w.y, ay); az = fmaf(dj, w.z, az); aw = fmaf(dj, w.w, aw);
    }
    const float sc = di / dg;
    float r0, r1, r2, r3;
    uint2 hi, lo;
    hi.x = pk_hi(sc * ax, sc * ay, r0, r1);
    hi.y = pk_hi(sc * az, sc * aw, r2, r3);
    lo.x = pk(r0, r1);
    lo.y = pk(r2, r3);
    const size_t e = ((size_t)b * NNODE * CCH + (size_t)node * CCH) / 4 + c4;
    ((uint2*)oh)[e] = hi;
    ((uint2*)ol)[e] = lo;
}

// ---------------- BN1 (4 blocks x 128 channels) ----------------
__global__ void bn1_kernel(const float* __restrict__ hp,
                           const float* __restrict__ g1, const float* __restrict__ beta1,
                           float* __restrict__ xg)
{
    const int c = blockIdx.x * 128 + threadIdx.x;
    float pooled[BATCH];
    float mu = 0.f;
    #pragma unroll
    for (int b = 0; b < BATCH; b++) {
        float s = 0.f;
        #pragma unroll 8
        for (int k = 0; k < 32; k++) s += hp[(size_t)(b * 32 + k) * CCH + c];
        pooled[b] = s * (1.f / (float)NNODE);
        mu += pooled[b];
    }
    mu *= (1.f / (float)BATCH);
    float var = 0.f;
    #pragma unroll
    for (int b = 0; b < BATCH; b++) { const float d = pooled[b] - mu; var = fmaf(d, d, var); }
    var *= (1.f / (float)BATCH);
    const float inv = rsqrtf(var + EPSV);
    const float ga = g1[c], be = beta1[c];
    #pragma unroll
    for (int b = 0; b < BATCH; b++)
        xg[b * CCH + c] = (pooled[b] - mu) * inv * ga + be;
}

// ---------------- BN2 scale/shift (4 blocks x 128 channels) ----------------
__global__ void stats_reduce_kernel(const float* __restrict__ rs, const float* __restrict__ rq,
                                    const float* __restrict__ xg,
                                    const float* __restrict__ g2, const float* __restrict__ beta2,
                                    float* __restrict__ scale, float* __restrict__ shift)
{
    const int c = blockIdx.x * 128 + threadIdx.x;
    float S = 0.f, Q = 0.f;
    #pragma unroll
    for (int b = 0; b < BATCH; b++) {
        float sb = 0.f, qb = 0.f;
        #pragma unroll 8
        for (int k = 0; k < 32; k++) {
            const size_t idx = (size_t)(b * 32 + k) * CCH + c;
            sb += rs[idx]; qb += rq[idx];
        }
        const float xv = xg[b * CCH + c];
        S += sb + 4096.f * xv;
        Q += qb + 2.f * xv * sb + 4096.f * xv * xv;
    }
    const float mu = S * (1.f / (float)MROWS);
    float var = Q * (1.f / (float)MROWS) - mu * mu;
    var = fmaxf(var, 0.f);
    const float inv = rsqrtf(var + EPSV);
    const float sc = inv * g2[c];
    scale[c] = sc;
    shift[c] = beta2[c] - mu * sc;
}

// ---------------- final: BN2 apply + transpose ----------------
__global__ void final_kernel(const float* __restrict__ res, const float* __restrict__ xg,
                             const float* __restrict__ scale, const float* __restrict__ shift,
                             float* __restrict__ out)
{
    __shared__ float tile[32][33];
    const int b = blockIdx.z;
    const int n0 = blockIdx.x * 32;
    const int c0 = blockIdx.y * 32;
    const int tx = threadIdx.x, ty = threadIdx.y;
    #pragma unroll
    for (int k = 0; k < 4; k++) {
        const int n = n0 + ty + k * 8;
        const int c = c0 + tx;
        tile[ty + k * 8][tx] = res[((size_t)b * NNODE + n) * CCH + c] + xg[b * CCH + c];
    }
    __syncthreads();
    #pragma unroll
    for (int k = 0; k < 4; k++) {
        const int c = c0 + ty + k * 8;
        const int n = n0 + tx;
        out[((size_t)b * CCH + c) * NNODE + n] = tile[tx][ty + k * 8] * scale[c] + shift[c];
    }
}

// ---------------- launch ----------------
extern "C" void kernel_launch(void* const* d_in, const int* in_sizes, int n_in,
                              void* d_out, int out_size)
{
    const float* x = nullptr;
    const float* w[4] = {nullptr, nullptr, nullptr, nullptr};
    const float* v[7] = {nullptr, nullptr, nullptr, nullptr, nullptr, nullptr, nullptr};
    int wi = 0, vi = 0;
    for (int i = 0; i < n_in; i++) {
        const int sz = in_sizes[i];
        if (sz == MROWS * CCH) { if (!x) x = (const float*)d_in[i]; }
        else if (sz == CCH * CCH) { if (wi < 4) w[wi++] = (const float*)d_in[i]; }
        else if (sz == CCH) { if (vi < 7) v[vi++] = (const float*)d_in[i]; }
    }
    const float* b_pre = v[0]; const float* b_g1 = v[1]; const float* b_g2 = v[2];
    const float* g1 = v[3];    const float* beta1 = v[4];
    const float* g2 = v[5];    const float* beta2 = v[6];

    float *p_res, *p_t, *p_hp, *p_rs, *p_rq, *p_xg, *p_sc, *p_sh;
    __nv_bfloat16 *p_ah, *p_al, *p_wh, *p_wl;
    cudaGetSymbolAddress((void**)&p_res, g_res);
    cudaGetSymbolAddress((void**)&p_t, g_t);
    cudaGetSymbolAddress((void**)&p_ah, g_ah);
    cudaGetSymbolAddress((void**)&p_al, g_al);
    cudaGetSymbolAddress((void**)&p_wh, g_wh);
    cudaGetSymbolAddress((void**)&p_wl, g_wl);
    cudaGetSymbolAddress((void**)&p_hp, g_hp);
    cudaGetSymbolAddress((void**)&p_rs, g_rs);
    cudaGetSymbolAddress((void**)&p_rq, g_rq);
    cudaGetSymbolAddress((void**)&p_xg, g_xg);
    cudaGetSymbolAddress((void**)&p_sc, g_scale);
    cudaGetSymbolAddress((void**)&p_sh, g_shift);

    float* out = (float*)d_out;

    cudaFuncSetAttribute(gemm_mma<0>, cudaFuncAttributeMaxDynamicSharedMemorySize, (int)GEMM_SMEM);
    cudaFuncSetAttribute(gemm_mma<1>, cudaFuncAttributeMaxDynamicSharedMemorySize, (int)GEMM_SMEM);

    const int agg_blocks = (BATCH * NNODE * (CCH / 4)) / 256;
    const size_t WB = (size_t)CCH * CCH;

    convert_w_kernel<<<dim3(16, 16, 4), dim3(32, 8)>>>(w[0], w[1], w[2], w[3], p_wh, p_wl);

    gemm_mma<1><<<dim3(8, 256), 256, GEMM_SMEM>>>(
        x, nullptr, p_wh, p_wl,
        p_res, p_t, nullptr, b_pre, p_rs, p_rq,
        /*mode0=*/1 | 8 | 16, /*mode1=*/1 | 4);

    agg_split_kernel<<<agg_blocks, 256>>>(p_t, p_ah, p_al);
    gemm_mma<0><<<dim3(4, 256), 256, GEMM_SMEM>>>(
        p_ah, p_al, p_wh + 2 * WB, p_wl + 2 * WB,
        p_t, p_t, b_g1, nullptr, nullptr, nullptr,
        /*mode0=*/1 | 2 | 4, /*mode1=*/0);
    agg_split_kernel<<<agg_blocks, 256>>>(p_t, p_ah, p_al);
    gemm_mma<0><<<dim3(4, 256), 256, GEMM_SMEM>>>(
        p_ah, p_al, p_wh + 3 * WB, p_wl + 3 * WB,
        nullptr, nullptr, b_g2, nullptr, p_hp, nullptr,
        /*mode0=*/2 | 4 | 8, /*mode1=*/0);

    bn1_kernel<<<4, 128>>>(p_hp, g1, beta1, p_xg);
    stats_reduce_kernel<<<4, 128>>>(p_rs, p_rq, p_xg, g2, beta2, p_sc, p_sh);
    final_kernel<<<dim3(NNODE / 32, CCH / 32, BATCH), dim3(32, 8)>>>(p_res, p_xg, p_sc, p_sh, out);
}

// round 7
// speedup vs baseline: 2.5299x; 1.0306x over previous
#include <cuda_runtime.h>
#include <cuda_bf16.h>
#include <cstdint>
#include <math.h>

#define BATCH 8
#define GH 64
#define GW 64
#define NNODE 4096
#define CCH 512
#define MROWS (BATCH * NNODE)
#define EPSV 1e-5f

// ---------------- scratch ----------------
__device__ float g_res[MROWS * CCH];
__device__ float g_t[MROWS * CCH];
__device__ __nv_bfloat16 g_ah[MROWS * CCH];
__device__ __nv_bfloat16 g_al[MROWS * CCH];
__device__ __nv_bfloat16 g_wh[4 * CCH * CCH];
__device__ __nv_bfloat16 g_wl[4 * CCH * CCH];
__device__ float g_hp[256 * CCH];
__device__ float g_rs[256 * CCH];
__device__ float g_rq[256 * CCH];
__device__ float g_xg[BATCH * CCH];
__device__ float g_scale[CCH];
__device__ float g_shift[CCH];

// ---------------- helpers ----------------
__device__ __forceinline__ uint32_t smem_u32(const void* p) {
    uint32_t a;
    asm("{ .reg .u64 t; cvta.to.shared.u64 t, %1; cvt.u32.u64 %0, t; }" : "=r"(a) : "l"(p));
    return a;
}
__device__ __forceinline__ void ldsm_x4(uint32_t addr, uint32_t* r) {
    asm volatile("ldmatrix.sync.aligned.m8n8.x4.shared.b16 {%0,%1,%2,%3}, [%4];"
                 : "=r"(r[0]), "=r"(r[1]), "=r"(r[2]), "=r"(r[3]) : "r"(addr));
}
__device__ __forceinline__ void mma16816(float* c, const uint32_t* a, const uint32_t* b) {
    asm volatile("mma.sync.aligned.m16n8k16.row.col.f32.bf16.bf16.f32 "
                 "{%0,%1,%2,%3}, {%4,%5,%6,%7}, {%8,%9}, {%0,%1,%2,%3};"
                 : "+f"(c[0]), "+f"(c[1]), "+f"(c[2]), "+f"(c[3])
                 : "r"(a[0]), "r"(a[1]), "r"(a[2]), "r"(a[3]), "r"(b[0]), "r"(b[1]));
}
__device__ __forceinline__ void cp16(uint32_t dst, const void* src) {
    asm volatile("cp.async.cg.shared.global [%0], [%1], 16;" :: "r"(dst), "l"(src) : "memory");
}
#define CP_COMMIT() asm volatile("cp.async.commit_group;" ::: "memory")
#define CP_WAIT0()  asm volatile("cp.async.wait_group 0;" ::: "memory")
#define CP_WAIT1()  asm volatile("cp.async.wait_group 1;" ::: "memory")

__device__ __forceinline__ uint32_t pk_hi(float x, float y, float& rx, float& ry) {
    __nv_bfloat16 hx = __float2bfloat16(x), hy = __float2bfloat16(y);
    rx = x - __bfloat162float(hx);
    ry = y - __bfloat162float(hy);
    return (uint32_t)__bfloat16_as_ushort(hx) | ((uint32_t)__bfloat16_as_ushort(hy) << 16);
}
__device__ __forceinline__ uint32_t pk(float x, float y) {
    return (uint32_t)__bfloat16_as_ushort(__float2bfloat16(x))
         | ((uint32_t)__bfloat16_as_ushort(__float2bfloat16(y)) << 16);
}

// ---------------- mma.sync split-bf16 GEMM, 3-stage SW128 pipeline -------------
// Combined tiles: A row r (128B) = [Ah 32 bf16 | Al 32 bf16], chunk16 j swizzled
// j^(r&7). B likewise. Stage = A tile 16KB + B tile 16KB = 32KB. 3 stages.
// mode bits: 1=store C, 2=relu, 4=bias, 8=column-sum partials, 16=also sumsq
#define TILE16 16384u
#define STAGEB 32768u
#define GEMM_SMEM (3u * STAGEB)

template<int AFP32>
__global__ __launch_bounds__(256, 2)
void gemm_mma(const void* __restrict__ A0, const void* __restrict__ A1,
              const __nv_bfloat16* __restrict__ Bh, const __nv_bfloat16* __restrict__ Bl,
              float* __restrict__ C0, float* __restrict__ C1,
              const float* __restrict__ bias0, const float* __restrict__ bias1,
              float* __restrict__ redS, float* __restrict__ redQ,
              int mode0, int mode1)
{
    extern __shared__ __align__(128) char smem[];
    const uint32_t sb = smem_u32(smem);
    const int tid = threadIdx.x;
    const int wid = tid >> 5;
    const int lane = tid & 31;
    const int wm = wid & 1;
    const int wn = wid >> 1;
    const int mtile = blockIdx.y;
    const int ntile = blockIdx.x;

    const __nv_bfloat16* src0 = (const __nv_bfloat16*)A0 + (size_t)mtile * 128 * 512;
    const __nv_bfloat16* src1 = (const __nv_bfloat16*)A1 + (size_t)mtile * 128 * 512;
    const float* srcx = (const float*)A0 + (size_t)mtile * 128 * 512;
    const __nv_bfloat16* src2 = Bh + (size_t)ntile * 128 * 512;
    const __nv_bfloat16* src3 = Bl + (size_t)ntile * 128 * 512;

    float acc[4][4][4];
    #pragma unroll
    for (int i = 0; i < 4; i++)
        #pragma unroll
        for (int j = 0; j < 4; j++)
            #pragma unroll
            for (int k = 0; k < 4; k++) acc[i][j][k] = 0.f;

    const int lr = lane & 15;
    const int lk = lane >> 4;
    const int bn = (lane & 7) + ((lane >> 4) << 3);
    const int bkc2 = (lane >> 3) & 1;   // B chunk low bit

    const int au_row[2] = { tid >> 2, (256 + tid) >> 2 };
    const int au_ch = tid & 3;
    float4 ra[2][2];

    // full stage load (A+B, 2048 chunks, 8/thread) -- bf16 A path
    #define LOAD_STAGE_BF16(kc, st) do { \
        const int _kc = (kc); const uint32_t _b = sb + (uint32_t)(st) * STAGEB; \
        _Pragma("unroll") \
        for (int p = 0; p < 8; p++) { \
            const int id = p * 256 + tid; \
            const int sel = id >> 10; \
            const int e = id & 1023; \
            const int row = e >> 3, j = e & 7; \
            const uint32_t dst = _b + (uint32_t)sel * TILE16 + (uint32_t)row * 128u \
                               + (uint32_t)((j ^ (row & 7)) << 4); \
            const __nv_bfloat16* s = (sel == 0 ? (j < 4 ? src0 : src1) : (j < 4 ? src2 : src3)) \
                                     + (size_t)row * 512 + (size_t)_kc * 32 + (j & 3) * 8; \
            cp16(dst, s); \
        } \
        CP_COMMIT(); \
    } while (0)

    // B-only stage load (1024 chunks, 4/thread) -- fp32 A path
    #define LOAD_STAGE_B(kc, st) do { \
        const int _kc = (kc); const uint32_t _b = sb + (uint32_t)(st) * STAGEB + TILE16; \
        _Pragma("unroll") \
        for (int p = 0; p < 4; p++) { \
            const int id = p * 256 + tid; \
            const int row = id >> 3, j = id & 7; \
            const uint32_t dst = _b + (uint32_t)row * 128u + (uint32_t)((j ^ (row & 7)) << 4); \
            const __nv_bfloat16* s = (j < 4 ? src2 : src3) \
                                     + (size_t)row * 512 + (size_t)_kc * 32 + (j & 3) * 8; \
            cp16(dst, s); \
        } \
        CP_COMMIT(); \
    } while (0)

    #define LOAD_A_F32(kc) do { \
        const int _kc = (kc); \
        _Pragma("unroll") \
        for (int i = 0; i < 2; i++) { \
            const float* s = srcx + (size_t)au_row[i] * 512 + (size_t)_kc * 32 + au_ch * 8; \
            ra[i][0] = *(const float4*)s; \
            ra[i][1] = *(const float4*)(s + 4); \
        } \
    } while (0)

    #define STORE_A_F32(st) do { \
        const uint32_t _b = sb + (uint32_t)(st) * STAGEB; \
        _Pragma("unroll") \
        for (int i = 0; i < 2; i++) { \
            float r0, r1, r2, r3, r4, r5, r6, r7; \
            uint4 hi, lo; \
            hi.x = pk_hi(ra[i][0].x, ra[i][0].y, r0, r1); \
            hi.y = pk_hi(ra[i][0].z, ra[i][0].w, r2, r3); \
            hi.z = pk_hi(ra[i][1].x, ra[i][1].y, r4, r5); \
            hi.w = pk_hi(ra[i][1].z, ra[i][1].w, r6, r7); \
            lo.x = pk(r0, r1); lo.y = pk(r2, r3); lo.z = pk(r4, r5); lo.w = pk(r6, r7); \
            const int sw = au_row[i] & 7; \
            *(uint4*)((char*)smem + (_b - sb) + (uint32_t)au_row[i] * 128u \
                      + (uint32_t)((au_ch ^ sw) << 4)) = hi; \
            *(uint4*)((char*)smem + (_b - sb) + (uint32_t)au_row[i] * 128u \
                      + (uint32_t)(((au_ch + 4) ^ sw) << 4)) = lo; \
        } \
    } while (0)

    // prologue: stages 0 and 1 in flight
    if (AFP32) {
        LOAD_A_F32(0); STORE_A_F32(0);
        LOAD_STAGE_B(0, 0);
        LOAD_STAGE_B(1, 1);
    } else {
        LOAD_STAGE_BF16(0, 0);
        LOAD_STAGE_BF16(1, 1);
    }

    #pragma unroll 1
    for (int kc = 0; kc < 16; kc++) {
        if (kc < 15) { CP_WAIT1(); } else { CP_WAIT0(); }
        __syncthreads();
        const int st = kc % 3;
        if (kc + 2 < 16) {
            const int st2 = (kc + 2) % 3;
            if (AFP32) LOAD_STAGE_B(kc + 2, st2);
            else       LOAD_STAGE_BF16(kc + 2, st2);
        }
        if (AFP32 && kc + 1 < 16) LOAD_A_F32(kc + 1);

        const uint32_t baseA = sb + (uint32_t)st * STAGEB;
        const uint32_t baseB = baseA + TILE16;
        #pragma unroll
        for (int ks = 0; ks < 2; ks++) {
            uint32_t ah[4][4], al[4][4];
            #pragma unroll
            for (int mi = 0; mi < 4; mi++) {
                const int R = wm * 64 + mi * 16 + lr;
                const int sw = R & 7;
                const int ch = 2 * ks + lk;
                ldsm_x4(baseA + (uint32_t)R * 128u + (uint32_t)((ch ^ sw) << 4), ah[mi]);
                ldsm_x4(baseA + (uint32_t)R * 128u + (uint32_t)(((ch + 4) ^ sw) << 4), al[mi]);
            }
            #pragma unroll
            for (int np = 0; np < 2; np++) {
                uint32_t bh[2][2], bl[2][2];
                const int R = wn * 32 + np * 16 + bn;
                const int sw = R & 7;
                const int ch = 2 * ks + bkc2;
                uint32_t r[4];
                ldsm_x4(baseB + (uint32_t)R * 128u + (uint32_t)((ch ^ sw) << 4), r);
                bh[0][0] = r[0]; bh[0][1] = r[1]; bh[1][0] = r[2]; bh[1][1] = r[3];
                ldsm_x4(baseB + (uint32_t)R * 128u + (uint32_t)(((ch + 4) ^ sw) << 4), r);
                bl[0][0] = r[0]; bl[0][1] = r[1]; bl[1][0] = r[2]; bl[1][1] = r[3];
                #pragma unroll
                for (int mi = 0; mi < 4; mi++)
                    #pragma unroll
                    for (int b2 = 0; b2 < 2; b2++) {
                        const int nb = np * 2 + b2;
                        mma16816(acc[mi][nb], ah[mi], bh[b2]);
                        mma16816(acc[mi][nb], ah[mi], bl[b2]);
                        mma16816(acc[mi][nb], al[mi], bh[b2]);
                    }
            }
        }
        if (AFP32 && kc + 1 < 16) STORE_A_F32((kc + 1) % 3);
    }

    // ---------------- epilogue ----------------
    const int selc = ntile >> 2;
    const int mode = selc ? mode1 : mode0;
    const float* bias = selc ? bias1 : bias0;
    float* C = selc ? C1 : C0;
    const int ncol = (ntile & 3) * 128;

    const int gid = lane >> 2;
    const int tig = lane & 3;

    float rsum[4][2], rq[4][2];
    #pragma unroll
    for (int nb = 0; nb < 4; nb++) { rsum[nb][0] = rsum[nb][1] = rq[nb][0] = rq[nb][1] = 0.f; }

    #pragma unroll
    for (int mi = 0; mi < 4; mi++) {
        const int row0 = mtile * 128 + wm * 64 + mi * 16 + gid;
        #pragma unroll
        for (int nb = 0; nb < 4; nb++) {
            const int col = ncol + wn * 32 + nb * 8 + tig * 2;
            float b0 = 0.f, b1 = 0.f;
            if (mode & 4) { b0 = __ldg(bias + col); b1 = __ldg(bias + col + 1); }
            float v0 = acc[mi][nb][0] + b0, v1 = acc[mi][nb][1] + b1;
            float v2 = acc[mi][nb][2] + b0, v3 = acc[mi][nb][3] + b1;
            if (mode & 2) {
                v0 = fmaxf(v0, 0.f); v1 = fmaxf(v1, 0.f);
                v2 = fmaxf(v2, 0.f); v3 = fmaxf(v3, 0.f);
            }
            if (mode & 1) {
                *(float2*)(C + (size_t)row0 * 512 + col) = make_float2(v0, v1);
                *(float2*)(C + (size_t)(row0 + 8) * 512 + col) = make_float2(v2, v3);
            }
            if (mode & 8) {
                rsum[nb][0] += v0 + v2; rsum[nb][1] += v1 + v3;
                if (mode & 16) {
                    rq[nb][0] = fmaf(v0, v0, fmaf(v2, v2, rq[nb][0]));
                    rq[nb][1] = fmaf(v1, v1, fmaf(v3, v3, rq[nb][1]));
                }
            }
        }
    }

    if (mode & 8) {
        #pragma unroll
        for (int nb = 0; nb < 4; nb++)
            #pragma unroll
            for (int j = 0; j < 2; j++) {
                #pragma unroll
                for (int m = 4; m <= 16; m <<= 1) {
                    rsum[nb][j] += __shfl_xor_sync(0xffffffffu, rsum[nb][j], m);
                    rq[nb][j]   += __shfl_xor_sync(0xffffffffu, rq[nb][j], m);
                }
            }
        __syncthreads();
        float* red = (float*)smem;
        if (gid == 0) {
            #pragma unroll
            for (int nb = 0; nb < 4; nb++) {
                const int c = wn * 32 + nb * 8 + tig * 2;
                red[wm * 128 + c]     = rsum[nb][0];
                red[wm * 128 + c + 1] = rsum[nb][1];
                red[256 + wm * 128 + c]     = rq[nb][0];
                red[256 + wm * 128 + c + 1] = rq[nb][1];
            }
        }
        __syncthreads();
        if (tid < 128) {
            const float s = red[tid] + red[128 + tid];
            redS[(size_t)mtile * 512 + ncol + tid] = s;
            if (mode & 16) {
                const float q = red[256 + tid] + red[384 + tid];
                redQ[(size_t)mtile * 512 + ncol + tid] = q;
            }
        }
    }
}

// ---------------- convert+transpose weights ----------------
__global__ void convert_w_kernel(const float* __restrict__ w0, const float* __restrict__ w1,
                                 const float* __restrict__ w2, const float* __restrict__ w3,
                                 __nv_bfloat16* __restrict__ wh, __nv_bfloat16* __restrict__ wl)
{
    __shared__ float t[32][33];
    const int wsel = blockIdx.z;
    const float* w = wsel == 0 ? w0 : wsel == 1 ? w1 : wsel == 2 ? w2 : w3;
    __nv_bfloat16* oh = wh + (size_t)wsel * CCH * CCH;
    __nv_bfloat16* ol = wl + (size_t)wsel * CCH * CCH;
    const int n0 = blockIdx.x * 32;
    const int k0 = blockIdx.y * 32;
    const int tx = threadIdx.x, ty = threadIdx.y;
    #pragma unroll
    for (int j = 0; j < 4; j++)
        t[ty + j * 8][tx] = w[(size_t)(k0 + ty + j * 8) * 512 + n0 + tx];
    __syncthreads();
    #pragma unroll
    for (int j = 0; j < 4; j++) {
        const float v = t[tx][ty + j * 8];
        const __nv_bfloat16 hb = __float2bfloat16(v);
        oh[(size_t)(n0 + ty + j * 8) * 512 + k0 + tx] = hb;
        ol[(size_t)(n0 + ty + j * 8) * 512 + k0 + tx] = __float2bfloat16(v - __bfloat162float(hb));
    }
}

// ---------------- GCN aggregation ----------------
__device__ __forceinline__ float degf(int r, int c) {
    return 1.f + (float)(c > 0) + (float)(c < GW - 1) + (float)(r > 0) + (float)(r < GH - 1);
}

__global__ void agg_split_kernel(const float* __restrict__ in,
                                 __nv_bfloat16* __restrict__ oh, __nv_bfloat16* __restrict__ ol)
{
    const int idx = blockIdx.x * 256 + threadIdx.x;
    const int c4 = idx & 127;
    const int node = (idx >> 7) & (NNODE - 1);
    const int b = idx >> 19;
    const int r = node >> 6;
    const int cc = node & 63;

    const float4* base = (const float4*)in + (size_t)b * NNODE * 128 + c4;
    const float dg = degf(r, cc);
    const float di = rsqrtf(dg);

    float4 v = base[(size_t)node * 128];
    float ax = di * v.x, ay = di * v.y, az = di * v.z, aw = di * v.w;
    if (cc > 0) {
        const float dj = rsqrtf(degf(r, cc - 1));
        float4 w = base[(size_t)(node - 1) * 128];
        ax = fmaf(dj, w.x, ax); ay = fmaf(dj, w.y, ay); az = fmaf(dj, w.z, az); aw = fmaf(dj, w.w, aw);
    }
    if (cc < GW - 1) {
        const float dj = rsqrtf(degf(r, cc + 1));
        float4 w = base[(size_t)(node + 1) * 128];
        ax = fmaf(dj, w.x, ax); ay = fmaf(dj, w.y, ay); az = fmaf(dj, w.z, az); aw = fmaf(dj, w.w, aw);
    }
    if (r > 0) {
        const float dj = rsqrtf(degf(r - 1, cc));
        float4 w = base[(size_t)(node - GW) * 128];
        ax = fmaf(dj, w.x, ax); ay = fmaf(dj, w.y, ay); az = fmaf(dj, w.z, az); aw = fmaf(dj, w.w, aw);
    }
    if (r < GH - 1) {
        const float dj = rsqrtf(degf(r + 1, cc));
        float4 w = base[(size_t)(node + GW) * 128];
        ax = fmaf(dj, w.x, ax); ay = fmaf(dj, w.y, ay); az = fmaf(dj, w.z, az); aw = fmaf(dj, w.w, aw);
    }
    const float sc = di / dg;
    float r0, r1, r2, r3;
    uint2 hi, lo;
    hi.x = pk_hi(sc * ax, sc * ay, r0, r1);
    hi.y = pk_hi(sc * az, sc * aw, r2, r3);
    lo.x = pk(r0, r1);
    lo.y = pk(r2, r3);
    const size_t e = ((size_t)b * NNODE * CCH + (size_t)node * CCH) / 4 + c4;
    ((uint2*)oh)[e] = hi;
    ((uint2*)ol)[e] = lo;
}

// ---------------- BN1 ----------------
__global__ void bn1_kernel(const float* __restrict__ hp,
                           const float* __restrict__ g1, const float* __restrict__ beta1,
                           float* __restrict__ xg)
{
    const int c = blockIdx.x * 128 + threadIdx.x;
    float pooled[BATCH];
    float mu = 0.f;
    #pragma unroll
    for (int b = 0; b < BATCH; b++) {
        float s = 0.f;
        #pragma unroll 8
        for (int k = 0; k < 32; k++) s += hp[(size_t)(b * 32 + k) * CCH + c];
        pooled[b] = s * (1.f / (float)NNODE);
        mu += pooled[b];
    }
    mu *= (1.f / (float)BATCH);
    float var = 0.f;
    #pragma unroll
    for (int b = 0; b < BATCH; b++) { const float d = pooled[b] - mu; var = fmaf(d, d, var); }
    var *= (1.f / (float)BATCH);
    const float inv = rsqrtf(var + EPSV);
    const float ga = g1[c], be = beta1[c];
    #pragma unroll
    for (int b = 0; b < BATCH; b++)
        xg[b * CCH + c] = (pooled[b] - mu) * inv * ga + be;
}

// ---------------- BN2 scale/shift ----------------
__global__ void stats_reduce_kernel(const float* __restrict__ rs, const float* __restrict__ rq,
                                    const float* __restrict__ xg,
                                    const float* __restrict__ g2, const float* __restrict__ beta2,
                                    float* __restrict__ scale, float* __restrict__ shift)
{
    const int c = blockIdx.x * 128 + threadIdx.x;
    float S = 0.f, Q = 0.f;
    #pragma unroll
    for (int b = 0; b < BATCH; b++) {
        float sb = 0.f, qb = 0.f;
        #pragma unroll 8
        for (int k = 0; k < 32; k++) {
            const size_t idx = (size_t)(b * 32 + k) * CCH + c;
            sb += rs[idx]; qb += rq[idx];
        }
        const float xv = xg[b * CCH + c];
        S += sb + 4096.f * xv;
        Q += qb + 2.f * xv * sb + 4096.f * xv * xv;
    }
    const float mu = S * (1.f / (float)MROWS);
    float var = Q * (1.f / (float)MROWS) - mu * mu;
    var = fmaxf(var, 0.f);
    const float inv = rsqrtf(var + EPSV);
    const float sc = inv * g2[c];
    scale[c] = sc;
    shift[c] = beta2[c] - mu * sc;
}

// ---------------- final: BN2 apply + transpose ----------------
__global__ void final_kernel(const float* __restrict__ res, const float* __restrict__ xg,
                             const float* __restrict__ scale, const float* __restrict__ shift,
                             float* __restrict__ out)
{
    __shared__ float tile[32][33];
    const int b = blockIdx.z;
    const int n0 = blockIdx.x * 32;
    const int c0 = blockIdx.y * 32;
    const int tx = threadIdx.x, ty = threadIdx.y;
    #pragma unroll
    for (int k = 0; k < 4; k++) {
        const int n = n0 + ty + k * 8;
        const int c = c0 + tx;
        tile[ty + k * 8][tx] = res[((size_t)b * NNODE + n) * CCH + c] + xg[b * CCH + c];
    }
    __syncthreads();
    #pragma unroll
    for (int k = 0; k < 4; k++) {
        const int c = c0 + ty + k * 8;
        const int n = n0 + tx;
        out[((size_t)b * CCH + c) * NNODE + n] = tile[tx][ty + k * 8] * scale[c] + shift[c];
    }
}

// ---------------- launch ----------------
extern "C" void kernel_launch(void* const* d_in, const int* in_sizes, int n_in,
                              void* d_out, int out_size)
{
    const float* x = nullptr;
    const float* w[4] = {nullptr, nullptr, nullptr, nullptr};
    const float* v[7] = {nullptr, nullptr, nullptr, nullptr, nullptr, nullptr, nullptr};
    int wi = 0, vi = 0;
    for (int i = 0; i < n_in; i++) {
        const int sz = in_sizes[i];
        if (sz == MROWS * CCH) { if (!x) x = (const float*)d_in[i]; }
        else if (sz == CCH * CCH) { if (wi < 4) w[wi++] = (const float*)d_in[i]; }
        else if (sz == CCH) { if (vi < 7) v[vi++] = (const float*)d_in[i]; }
    }
    const float* b_pre = v[0]; const float* b_g1 = v[1]; const float* b_g2 = v[2];
    const float* g1 = v[3];    const float* beta1 = v[4];
    const float* g2 = v[5];    const float* beta2 = v[6];

    float *p_res, *p_t, *p_hp, *p_rs, *p_rq, *p_xg, *p_sc, *p_sh;
    __nv_bfloat16 *p_ah, *p_al, *p_wh, *p_wl;
    cudaGetSymbolAddress((void**)&p_res, g_res);
    cudaGetSymbolAddress((void**)&p_t, g_t);
    cudaGetSymbolAddress((void**)&p_ah, g_ah);
    cudaGetSymbolAddress((void**)&p_al, g_al);
    cudaGetSymbolAddress((void**)&p_wh, g_wh);
    cudaGetSymbolAddress((void**)&p_wl, g_wl);
    cudaGetSymbolAddress((void**)&p_hp, g_hp);
    cudaGetSymbolAddress((void**)&p_rs, g_rs);
    cudaGetSymbolAddress((void**)&p_rq, g_rq);
    cudaGetSymbolAddress((void**)&p_xg, g_xg);
    cudaGetSymbolAddress((void**)&p_sc, g_scale);
    cudaGetSymbolAddress((void**)&p_sh, g_shift);

    float* out = (float*)d_out;

    cudaFuncSetAttribute(gemm_mma<0>, cudaFuncAttributeMaxDynamicSharedMemorySize, (int)GEMM_SMEM);
    cudaFuncSetAttribute(gemm_mma<1>, cudaFuncAttributeMaxDynamicSharedMemorySize, (int)GEMM_SMEM);

    const int agg_blocks = (BATCH * NNODE * (CCH / 4)) / 256;
    const size_t WB = (size_t)CCH * CCH;

    convert_w_kernel<<<dim3(16, 16, 4), dim3(32, 8)>>>(w[0], w[1], w[2], w[3], p_wh, p_wl);

    gemm_mma<1><<<dim3(8, 256), 256, GEMM_SMEM>>>(
        x, nullptr, p_wh, p_wl,
        p_res, p_t, nullptr, b_pre, p_rs, p_rq,
        /*mode0=*/1 | 8 | 16, /*mode1=*/1 | 4);

    agg_split_kernel<<<agg_blocks, 256>>>(p_t, p_ah, p_al);
    gemm_mma<0><<<dim3(4, 256), 256, GEMM_SMEM>>>(
        p_ah, p_al, p_wh + 2 * WB, p_wl + 2 * WB,
        p_t, p_t, b_g1, nullptr, nullptr, nullptr,
        /*mode0=*/1 | 2 | 4, /*mode1=*/0);
    agg_split_kernel<<<agg_blocks, 256>>>(p_t, p_ah, p_al);
    gemm_mma<0><<<dim3(4, 256), 256, GEMM_SMEM>>>(
        p_ah, p_al, p_wh + 3 * WB, p_wl + 3 * WB,
        nullptr, nullptr, b_g2, nullptr, p_hp, nullptr,
        /*mode0=*/2 | 4 | 8, /*mode1=*/0);

    bn1_kernel<<<4, 128>>>(p_hp, g1, beta1, p_xg);
    stats_reduce_kernel<<<4, 128>>>(p_rs, p_rq, p_xg, g2, beta2, p_sc, p_sh);
    final_kernel<<<dim3(NNODE / 32, CCH / 32, BATCH), dim3(32, 8)>>>(p_res, p_xg, p_sc, p_sh, out);
}